// round 7
// baseline (speedup 1.0000x reference)
#include <cuda_runtime.h>
#include <cuda_bf16.h>
#include <cstdint>

// ---------------- static problem configuration ----------------
#define TOTAL    6848
#define D_MODEL  768
#define D_INNER  1536
#define D_STATE  16
#define DT_RANK  48
#define NSUBJ    8
#define N_LAYERS 2
#define EPS      1e-5f

__constant__ int c_offsets[NSUBJ + 1] = {0, 1024, 1920, 2688, 3712, 4224, 4864, 5824, 6848};

#define IPW_N (2 * D_INNER * D_MODEL)
#define XPW_N ((DT_RANK + 2 * D_STATE) * D_INNER)
#define DTW_N (D_INNER * DT_RANK)
#define OPW_N (D_MODEL * D_INNER)

// ---------------- scratch (device globals; no runtime allocation) ----------------
__device__ float g_h  [TOTAL * D_MODEL];
__device__ float g_xz [TOTAL * 2 * D_INNER];
__device__ float g_xc [TOTAL * D_INNER];
__device__ float g_dbl[TOTAL * 80];
__device__ float g_dt [TOTAL * D_INNER];

__device__ __nv_bfloat16 g_hn_hi[TOTAL * D_MODEL],  g_hn_lo[TOTAL * D_MODEL];
__device__ __nv_bfloat16 g_xc_hi[TOTAL * D_INNER],  g_xc_lo[TOTAL * D_INNER];
__device__ __nv_bfloat16 g_db_hi[TOTAL * DT_RANK],  g_db_lo[TOTAL * DT_RANK];
__device__ __nv_bfloat16 g_y_hi [TOTAL * D_INNER],  g_y_lo [TOTAL * D_INNER];

__device__ __nv_bfloat16 g_ip_hi[N_LAYERS * IPW_N], g_ip_lo[N_LAYERS * IPW_N];
__device__ __nv_bfloat16 g_xp_hi[N_LAYERS * XPW_N], g_xp_lo[N_LAYERS * XPW_N];
__device__ __nv_bfloat16 g_dw_hi[N_LAYERS * DTW_N], g_dw_lo[N_LAYERS * DTW_N];
__device__ __nv_bfloat16 g_op_hi[N_LAYERS * OPW_N], g_op_lo[N_LAYERS * OPW_N];

// ---------------- helpers ----------------
__device__ __forceinline__ float blockReduceSum(float v) {
    __shared__ float sh[8];
    __shared__ float total;
    #pragma unroll
    for (int o = 16; o; o >>= 1) v += __shfl_xor_sync(0xffffffffu, v, o);
    if ((threadIdx.x & 31) == 0) sh[threadIdx.x >> 5] = v;
    __syncthreads();
    v = (threadIdx.x < 8) ? sh[threadIdx.x] : 0.f;
    #pragma unroll
    for (int o = 4; o; o >>= 1) v += __shfl_xor_sync(0xffffffffu, v, o);
    if (threadIdx.x == 0) total = v;
    __syncthreads();
    return total;
}

__device__ __forceinline__ float silu_f(float x) { return x / (1.f + __expf(-x)); }

__device__ __forceinline__ void split2v(float f0, float f1,
                                        __nv_bfloat162& hi, __nv_bfloat162& lo) {
    hi = __floats2bfloat162_rn(f0, f1);
    lo = __floats2bfloat162_rn(f0 - __bfloat162float(hi.x), f1 - __bfloat162float(hi.y));
}

__device__ __forceinline__ void mma_bf16(float* c, const uint32_t* a, uint32_t b0, uint32_t b1) {
    asm volatile(
        "mma.sync.aligned.m16n8k16.row.col.f32.bf16.bf16.f32 "
        "{%0,%1,%2,%3}, {%4,%5,%6,%7}, {%8,%9}, {%0,%1,%2,%3};"
        : "+f"(c[0]), "+f"(c[1]), "+f"(c[2]), "+f"(c[3])
        : "r"(a[0]), "r"(a[1]), "r"(a[2]), "r"(a[3]), "r"(b0), "r"(b1));
}

__device__ __forceinline__ void ldsm4(uint32_t* r, uint32_t addr) {
    asm volatile("ldmatrix.sync.aligned.m8n8.x4.shared.b16 {%0,%1,%2,%3}, [%4];"
        : "=r"(r[0]), "=r"(r[1]), "=r"(r[2]), "=r"(r[3]) : "r"(addr));
}

__device__ __forceinline__ void cp16(uint32_t dst, const void* src, int sz) {
    asm volatile("cp.async.cg.shared.global [%0], [%1], 16, %2;"
                 :: "r"(dst), "l"(src), "r"(sz));
}
#define CP_COMMIT() asm volatile("cp.async.commit_group;")
#define CP_WAIT(n)  asm volatile("cp.async.wait_group %0;" :: "n"(n))

// swizzled smem byte offset inside one [rows]x32 bf16 tile (64B rows)
__device__ __forceinline__ uint32_t sw_off(int row, int chunk) {
    return (uint32_t)(row * 64 + ((chunk ^ ((row >> 1) & 3)) << 4));
}

// ---------------- weight / activation split kernels ----------------
__global__ void __launch_bounds__(256) split_kernel(
    const float* __restrict__ src, __nv_bfloat16* __restrict__ hi,
    __nv_bfloat16* __restrict__ lo, int n4)
{
    int i = blockIdx.x * 256 + threadIdx.x;
    if (i >= n4) return;
    float4 v = ((const float4*)src)[i];
    __nv_bfloat162 h0, l0, h1, l1;
    split2v(v.x, v.y, h0, l0);
    split2v(v.z, v.w, h1, l1);
    ((__nv_bfloat162*)hi)[i * 2]     = h0;
    ((__nv_bfloat162*)hi)[i * 2 + 1] = h1;
    ((__nv_bfloat162*)lo)[i * 2]     = l0;
    ((__nv_bfloat162*)lo)[i * 2 + 1] = l1;
}

__global__ void __launch_bounds__(256) split48_kernel(
    const float* __restrict__ src, __nv_bfloat16* __restrict__ hi,
    __nv_bfloat16* __restrict__ lo)
{
    int p = blockIdx.x * 256 + threadIdx.x;
    if (p >= TOTAL * 24) return;
    int row = p / 24, cp = p % 24;
    const float* s = src + (size_t)row * 80 + cp * 2;
    __nv_bfloat162 h, l;
    split2v(s[0], s[1], h, l);
    ((__nv_bfloat162*)hi)[row * 24 + cp] = h;
    ((__nv_bfloat162*)lo)[row * 24 + cp] = l;
}

// ---------------- embed gather + rmsnorm (fp32 residual) ----------------
__global__ void __launch_bounds__(256) embed_rms_kernel(
    const int* __restrict__ tokens, const float* __restrict__ embed,
    const float* __restrict__ w, float* __restrict__ out)
{
    const int row = blockIdx.x;
    const float* xr = embed + (size_t)tokens[row] * D_MODEL;
    float s = 0.f;
    for (int i = threadIdx.x; i < D_MODEL; i += 256) { float v = xr[i]; s += v * v; }
    float tot = blockReduceSum(s);
    float r = rsqrtf(tot / D_MODEL + EPS);
    for (int i = threadIdx.x; i < D_MODEL; i += 256)
        out[row * D_MODEL + i] = xr[i] * r * w[i];
}

// ---------------- rmsnorm -> bf16 hi/lo ----------------
__global__ void __launch_bounds__(256) rms_split_kernel(
    const float* __restrict__ x, const float* __restrict__ w,
    __nv_bfloat16* __restrict__ hi, __nv_bfloat16* __restrict__ lo)
{
    const int row = blockIdx.x;
    const float* xr = x + row * D_MODEL;
    float s = 0.f;
    for (int i = threadIdx.x; i < D_MODEL; i += 256) { float v = xr[i]; s += v * v; }
    float tot = blockReduceSum(s);
    float r = rsqrtf(tot / D_MODEL + EPS);
    for (int p = threadIdx.x; p < D_MODEL / 2; p += 256) {
        float2 v = ((const float2*)xr)[p];
        float a = v.x * r * w[p * 2], b = v.y * r * w[p * 2 + 1];
        __nv_bfloat162 h, l;
        split2v(a, b, h, l);
        ((__nv_bfloat162*)hi)[row * (D_MODEL / 2) + p] = h;
        ((__nv_bfloat162*)lo)[row * (D_MODEL / 2) + p] = l;
    }
}

// ---------------- final: rmsnorm(norm_f) then rmsnorm(out_norm) ----------------
__global__ void __launch_bounds__(256) final_kernel(
    const float* __restrict__ x, const float* __restrict__ wf,
    const float* __restrict__ wo, float* __restrict__ out)
{
    const int row = blockIdx.x;
    const float* xr = x + row * D_MODEL;
    float s1 = 0.f, s2 = 0.f;
    for (int i = threadIdx.x; i < D_MODEL; i += 256) {
        float v = xr[i];
        float vw = v * wf[i];
        s1 += v * v;
        s2 += vw * vw;
    }
    float t1 = blockReduceSum(s1);
    float t2 = blockReduceSum(s2);
    float r1 = rsqrtf(t1 / D_MODEL + EPS);
    float m2 = (r1 * r1) * t2 / D_MODEL;
    float r2 = rsqrtf(m2 + EPS);
    for (int i = threadIdx.x; i < D_MODEL; i += 256)
        out[row * D_MODEL + i] = xr[i] * wf[i] * r1 * r2 * wo[i];
}

// ---------------- tensor-core GEMM (legacy mma.sync, split-bf16 3-term) ----------
// C[M,N] (op)= A[M,K] * W[N,K]^T, operands pre-split bf16 hi/lo.
// CTA tile 128x256, 512 threads (16 warps, warp tile 64x32), BK=32,
// 2-stage cp.async double buffer, ldmatrix fragments, XOR-swizzled smem.
// epi: 0 = store, 1 = softplus(acc + bias[n]), 2 = C += acc
#define GS_A_HI 0
#define GS_A_LO 8192
#define GS_B_HI 16384
#define GS_B_LO 32768
#define GS_STAGE 49152
#define GSMEM (2 * GS_STAGE)

__device__ __forceinline__ void gemm_load_stage(
    uint32_t sb, int tid, int m0, int n0, int k0, int M, int N, int K,
    const __nv_bfloat16* __restrict__ Ah, const __nv_bfloat16* __restrict__ Al,
    const __nv_bfloat16* __restrict__ Wh, const __nv_bfloat16* __restrict__ Wl)
{
    // A: 128 rows x 4 chunks = 512 (row,chunk) pairs
    {
        int row = tid >> 2, c = tid & 3;
        int k = k0 + c * 8;
        int kin = (k < K) ? 16 : 0;
        int kc  = (k < K) ? k : 0;
        uint32_t off = sw_off(row, c);
        int ar = m0 + row; if (ar >= M) ar = M - 1;
        size_t ao = (size_t)ar * K + kc;
        cp16(sb + GS_A_HI + off, Ah + ao, kin);
        cp16(sb + GS_A_LO + off, Al + ao, kin);
    }
    // B: 256 rows x 4 chunks = 1024 pairs
    #pragma unroll
    for (int i = 0; i < 2; i++) {
        int lj = i * 512 + tid;
        int row = lj >> 2, c = lj & 3;
        int k = k0 + c * 8;
        int kin = (k < K) ? 16 : 0;
        int kc  = (k < K) ? k : 0;
        uint32_t off = sw_off(row, c);
        int br = n0 + row;
        int bin = (br < N) ? kin : 0;
        int brc = (br < N) ? br : 0;
        size_t bo = (size_t)brc * K + kc;
        cp16(sb + GS_B_HI + off, Wh + bo, bin);
        cp16(sb + GS_B_LO + off, Wl + bo, bin);
    }
}

__global__ void __launch_bounds__(512) gemm_tc_kernel(
    const __nv_bfloat16* __restrict__ Ah, const __nv_bfloat16* __restrict__ Al,
    const __nv_bfloat16* __restrict__ Wh, const __nv_bfloat16* __restrict__ Wl,
    const float* __restrict__ bias, float* __restrict__ C,
    int M, int N, int K, int epi)
{
    extern __shared__ uint8_t smem[];
    const int tid = threadIdx.x, lane = tid & 31, warp = tid >> 5;
    const int m0 = blockIdx.y * 128, n0 = blockIdx.x * 256;
    const int wm = (warp & 1) * 64, wn = (warp >> 1) * 32;
    const int g = lane >> 2, tg = lane & 3;

    uint32_t sbase = (uint32_t)__cvta_generic_to_shared(smem);

    float acc[4][4][4];
    #pragma unroll
    for (int mi = 0; mi < 4; mi++)
        #pragma unroll
        for (int ni = 0; ni < 4; ni++)
            #pragma unroll
            for (int r = 0; r < 4; r++) acc[mi][ni][r] = 0.f;

    const int KT = (K + 31) >> 5;
    gemm_load_stage(sbase, tid, m0, n0, 0, M, N, K, Ah, Al, Wh, Wl);
    CP_COMMIT();

    const int mat = lane >> 3, mr = lane & 7;

    for (int kt = 0; kt < KT; kt++) {
        if (kt + 1 < KT) {
            gemm_load_stage(sbase + ((kt + 1) & 1) * GS_STAGE, tid, m0, n0,
                            (kt + 1) * 32, M, N, K, Ah, Al, Wh, Wl);
            CP_COMMIT();
            CP_WAIT(1);
        } else {
            CP_WAIT(0);
        }
        __syncthreads();

        uint32_t stb  = sbase + (kt & 1) * GS_STAGE;
        uint32_t Ah_b = stb + GS_A_HI, Al_b = stb + GS_A_LO;
        uint32_t Bh_b = stb + GS_B_HI, Bl_b = stb + GS_B_LO;

        #pragma unroll
        for (int s = 0; s < 2; s++) {
            // B fragments: two x4 per precision cover 4 n-groups (n8 each)
            uint32_t bh[4][2], bl[4][2];
            #pragma unroll
            for (int pair = 0; pair < 2; pair++) {
                int nrow = wn + pair * 16 + ((mat >> 1) << 3) + mr;
                int chunk = s * 2 + (mat & 1);
                uint32_t off = sw_off(nrow, chunk);
                uint32_t r[4];
                ldsm4(r, Bh_b + off);
                bh[pair * 2][0] = r[0]; bh[pair * 2][1] = r[1];
                bh[pair * 2 + 1][0] = r[2]; bh[pair * 2 + 1][1] = r[3];
                ldsm4(r, Bl_b + off);
                bl[pair * 2][0] = r[0]; bl[pair * 2][1] = r[1];
                bl[pair * 2 + 1][0] = r[2]; bl[pair * 2 + 1][1] = r[3];
            }
            #pragma unroll
            for (int mi = 0; mi < 4; mi++) {
                int arow = wm + mi * 16 + ((mat & 1) << 3) + mr;
                int chunk = s * 2 + (mat >> 1);
                uint32_t off = sw_off(arow, chunk);
                uint32_t ah[4], al[4];
                ldsm4(ah, Ah_b + off);
                ldsm4(al, Al_b + off);
                #pragma unroll
                for (int ni = 0; ni < 4; ni++) {
                    mma_bf16(acc[mi][ni], ah, bh[ni][0], bh[ni][1]);
                    mma_bf16(acc[mi][ni], ah, bl[ni][0], bl[ni][1]);
                    mma_bf16(acc[mi][ni], al, bh[ni][0], bh[ni][1]);
                }
            }
        }
        __syncthreads();
    }

    // ---- epilogue ----
    #pragma unroll
    for (int mi = 0; mi < 4; mi++) {
        int mrow0 = m0 + wm + mi * 16 + g;
        int mrow1 = mrow0 + 8;
        #pragma unroll
        for (int ni = 0; ni < 4; ni++) {
            int n = n0 + wn + ni * 8 + 2 * tg;
            if (n >= N) continue;   // N multiple of 8 -> pair-safe
            float* c = acc[mi][ni];
            if (epi == 1) {
                float b0 = bias[n], b1 = bias[n + 1];
                #pragma unroll
                for (int r = 0; r < 4; r++) {
                    float v = c[r] + ((r & 1) ? b1 : b0);
                    c[r] = (v > 20.f) ? v : log1pf(__expf(v));
                }
            }
            if (mrow0 < M) {
                size_t b = (size_t)mrow0 * N + n;
                if (epi == 2) { C[b] += c[0]; C[b + 1] += c[1]; }
                else          { C[b]  = c[0]; C[b + 1]  = c[1]; }
            }
            if (mrow1 < M) {
                size_t b = (size_t)mrow1 * N + n;
                if (epi == 2) { C[b] += c[2]; C[b + 1] += c[3]; }
                else          { C[b]  = c[2]; C[b + 1]  = c[3]; }
            }
        }
    }
}

// ---------------- causal depthwise conv (k=4) + bias + silu (+ split) ----------------
__global__ void __launch_bounds__(256) conv_kernel(
    const float* __restrict__ xz, const float* __restrict__ cw,
    const float* __restrict__ cb, float* __restrict__ xc,
    __nv_bfloat16* __restrict__ xc_hi, __nv_bfloat16* __restrict__ xc_lo)
{
    int p = blockIdx.x * 256 + threadIdx.x;
    if (p >= TOTAL * (D_INNER / 2)) return;
    int t = p / (D_INNER / 2);
    int i = (p - t * (D_INNER / 2)) * 2;
    int t0 = 0;
    #pragma unroll
    for (int s = 1; s < NSUBJ; s++)
        if (t >= c_offsets[s]) t0 = c_offsets[s];

    float o[2];
    #pragma unroll
    for (int u = 0; u < 2; u++) {
        int ch = i + u;
        float w0 = cw[ch * 4 + 0], w1 = cw[ch * 4 + 1], w2 = cw[ch * 4 + 2], w3 = cw[ch * 4 + 3];
        float acc = cb[ch] + w3 * xz[(size_t)t * (2 * D_INNER) + ch];
        if (t - 1 >= t0) acc = fmaf(w2, xz[(size_t)(t - 1) * (2 * D_INNER) + ch], acc);
        if (t - 2 >= t0) acc = fmaf(w1, xz[(size_t)(t - 2) * (2 * D_INNER) + ch], acc);
        if (t - 3 >= t0) acc = fmaf(w0, xz[(size_t)(t - 3) * (2 * D_INNER) + ch], acc);
        o[u] = silu_f(acc);
    }
    ((float2*)xc)[p] = make_float2(o[0], o[1]);
    __nv_bfloat162 h, l;
    split2v(o[0], o[1], h, l);
    ((__nv_bfloat162*)xc_hi)[p] = h;
    ((__nv_bfloat162*)xc_lo)[p] = l;
}

// ---------------- selective scan (+ D skip + silu(z) gate), split output ----------------
__global__ void __launch_bounds__(256) scan_kernel(
    const float* __restrict__ xc, const float* __restrict__ dt,
    const float* __restrict__ dbl, const float* __restrict__ xz,
    const float* __restrict__ A_log, const float* __restrict__ Dp,
    __nv_bfloat16* __restrict__ y_hi, __nv_bfloat16* __restrict__ y_lo)
{
    const int subj = blockIdx.y;
    const int d0 = blockIdx.x * 16;
    const int off = c_offsets[subj];
    const int L = c_offsets[subj + 1] - off;
    const int tid = threadIdx.x;
    const int dl = tid >> 4;
    const int n  = tid & 15;
    const int d  = d0 + dl;

    const float Acoef = -__expf(A_log[d * D_STATE + n]);
    const float Dv = Dp[d];
    float hc = 0.f;

    __shared__ float sh_dt[64][16], sh_x[64][16], sh_z[64][16], sh_B[64][16], sh_C[64][16];

    for (int tb = 0; tb < L; tb += 64) {
        int nsteps = min(64, L - tb);
        for (int idx = tid; idx < 64 * 16; idx += 256) {
            int tl = idx >> 4, dd = idx & 15;
            if (tl < nsteps) {
                int t = off + tb + tl;
                sh_dt[tl][dd] = dt[(size_t)t * D_INNER + d0 + dd];
                sh_x [tl][dd] = xc[(size_t)t * D_INNER + d0 + dd];
                sh_z [tl][dd] = xz[(size_t)t * (2 * D_INNER) + D_INNER + d0 + dd];
                sh_B [tl][dd] = dbl[(size_t)t * 80 + DT_RANK + dd];
                sh_C [tl][dd] = dbl[(size_t)t * 80 + DT_RANK + D_STATE + dd];
            }
        }
        __syncthreads();
        for (int s = 0; s < nsteps; s++) {
            float dtv = sh_dt[s][dl];
            float xv  = sh_x[s][dl];
            float dA = __expf(dtv * Acoef);
            hc = fmaf(dA, hc, (dtv * xv) * sh_B[s][n]);
            float p = hc * sh_C[s][n];
            p += __shfl_xor_sync(0xffffffffu, p, 1);
            p += __shfl_xor_sync(0xffffffffu, p, 2);
            p += __shfl_xor_sync(0xffffffffu, p, 4);
            p += __shfl_xor_sync(0xffffffffu, p, 8);
            if (n == 0) {
                float yv = p + xv * Dv;
                yv *= silu_f(sh_z[s][dl]);
                __nv_bfloat16 h = __float2bfloat16_rn(yv);
                __nv_bfloat16 l = __float2bfloat16_rn(yv - __bfloat162float(h));
                size_t o = (size_t)(off + tb + s) * D_INNER + d;
                y_hi[o] = h;
                y_lo[o] = l;
            }
        }
        __syncthreads();
    }
}

// ---------------- launch ----------------
extern "C" void kernel_launch(void* const* d_in, const int* in_sizes, int n_in,
                              void* d_out, int out_size) {
    const int*   tokens     = (const int*)  d_in[0];
    const float* embed      = (const float*)d_in[1];
    const float* in_norm_w  = (const float*)d_in[2];
    const float* out_norm_w = (const float*)d_in[3];
    const float* norm_w     = (const float*)d_in[4];
    const float* in_proj_w  = (const float*)d_in[5];
    const float* conv_w     = (const float*)d_in[6];
    const float* conv_b     = (const float*)d_in[7];
    const float* x_proj_w   = (const float*)d_in[8];
    const float* dt_proj_w  = (const float*)d_in[9];
    const float* dt_proj_b  = (const float*)d_in[10];
    const float* A_log      = (const float*)d_in[11];
    const float* D_param    = (const float*)d_in[12];
    const float* out_proj_w = (const float*)d_in[13];
    const float* norm_f_w   = (const float*)d_in[14];
    float* out = (float*)d_out;

    float *h, *xz, *xc, *dbl, *dt;
    __nv_bfloat16 *hn_hi, *hn_lo, *xc_hi, *xc_lo, *db_hi, *db_lo, *y_hi, *y_lo;
    __nv_bfloat16 *ip_hi, *ip_lo, *xp_hi, *xp_lo, *dw_hi, *dw_lo, *op_hi, *op_lo;
    cudaGetSymbolAddress((void**)&h,   g_h);
    cudaGetSymbolAddress((void**)&xz,  g_xz);
    cudaGetSymbolAddress((void**)&xc,  g_xc);
    cudaGetSymbolAddress((void**)&dbl, g_dbl);
    cudaGetSymbolAddress((void**)&dt,  g_dt);
    cudaGetSymbolAddress((void**)&hn_hi, g_hn_hi); cudaGetSymbolAddress((void**)&hn_lo, g_hn_lo);
    cudaGetSymbolAddress((void**)&xc_hi, g_xc_hi); cudaGetSymbolAddress((void**)&xc_lo, g_xc_lo);
    cudaGetSymbolAddress((void**)&db_hi, g_db_hi); cudaGetSymbolAddress((void**)&db_lo, g_db_lo);
    cudaGetSymbolAddress((void**)&y_hi,  g_y_hi);  cudaGetSymbolAddress((void**)&y_lo,  g_y_lo);
    cudaGetSymbolAddress((void**)&ip_hi, g_ip_hi); cudaGetSymbolAddress((void**)&ip_lo, g_ip_lo);
    cudaGetSymbolAddress((void**)&xp_hi, g_xp_hi); cudaGetSymbolAddress((void**)&xp_lo, g_xp_lo);
    cudaGetSymbolAddress((void**)&dw_hi, g_dw_hi); cudaGetSymbolAddress((void**)&dw_lo, g_dw_lo);
    cudaGetSymbolAddress((void**)&op_hi, g_op_hi); cudaGetSymbolAddress((void**)&op_lo, g_op_lo);

    cudaFuncSetAttribute(gemm_tc_kernel, cudaFuncAttributeMaxDynamicSharedMemorySize, GSMEM);

    const int MB = (TOTAL + 127) / 128;   // 54

    // one-time per launch: split all weights to bf16 hi/lo
    split_kernel<<<(N_LAYERS * IPW_N / 4 + 255) / 256, 256>>>(in_proj_w,  ip_hi, ip_lo, N_LAYERS * IPW_N / 4);
    split_kernel<<<(N_LAYERS * XPW_N / 4 + 255) / 256, 256>>>(x_proj_w,   xp_hi, xp_lo, N_LAYERS * XPW_N / 4);
    split_kernel<<<(N_LAYERS * DTW_N / 4 + 255) / 256, 256>>>(dt_proj_w,  dw_hi, dw_lo, N_LAYERS * DTW_N / 4);
    split_kernel<<<(N_LAYERS * OPW_N / 4 + 255) / 256, 256>>>(out_proj_w, op_hi, op_lo, N_LAYERS * OPW_N / 4);

    embed_rms_kernel<<<TOTAL, 256>>>(tokens, embed, in_norm_w, h);

    for (int l = 0; l < N_LAYERS; l++) {
        rms_split_kernel<<<TOTAL, 256>>>(h, norm_w + l * D_MODEL, hn_hi, hn_lo);

        // xz = hn @ in_proj_w^T   [TOTAL, 3072]
        gemm_tc_kernel<<<dim3(2 * D_INNER / 256, MB), 512, GSMEM>>>(
            hn_hi, hn_lo, ip_hi + (size_t)l * IPW_N, ip_lo + (size_t)l * IPW_N,
            nullptr, xz, TOTAL, 2 * D_INNER, D_MODEL, 0);

        conv_kernel<<<(TOTAL * D_INNER / 2 + 255) / 256, 256>>>(
            xz, conv_w + (size_t)l * D_INNER * 4, conv_b + (size_t)l * D_INNER,
            xc, xc_hi, xc_lo);

        // dbl = xc @ x_proj_w^T   [TOTAL, 80]
        gemm_tc_kernel<<<dim3(1, MB), 512, GSMEM>>>(
            xc_hi, xc_lo, xp_hi + (size_t)l * XPW_N, xp_lo + (size_t)l * XPW_N,
            nullptr, dbl, TOTAL, 80, D_INNER, 0);

        split48_kernel<<<(TOTAL * 24 + 255) / 256, 256>>>(dbl, db_hi, db_lo);

        // dt = softplus(dbl[:, :48] @ dt_proj_w^T + b)   [TOTAL, 1536]
        gemm_tc_kernel<<<dim3(D_INNER / 256, MB), 512, GSMEM>>>(
            db_hi, db_lo, dw_hi + (size_t)l * DTW_N, dw_lo + (size_t)l * DTW_N,
            dt_proj_b + (size_t)l * D_INNER, dt, TOTAL, D_INNER, DT_RANK, 1);

        scan_kernel<<<dim3(D_INNER / 16, NSUBJ), 256>>>(
            xc, dt, dbl, xz,
            A_log + (size_t)l * D_INNER * D_STATE, D_param + (size_t)l * D_INNER,
            y_hi, y_lo);

        // h += y @ out_proj_w^T   [TOTAL, 768]
        gemm_tc_kernel<<<dim3(D_MODEL / 256, MB), 512, GSMEM>>>(
            y_hi, y_lo, op_hi + (size_t)l * OPW_N, op_lo + (size_t)l * OPW_N,
            nullptr, h, TOTAL, D_MODEL, D_INNER, 2);
    }

    final_kernel<<<TOTAL, 256>>>(h, norm_f_w, out_norm_w, out);
}

// round 13
// speedup vs baseline: 1.0602x; 1.0602x over previous
#include <cuda_runtime.h>
#include <cuda_bf16.h>
#include <cstdint>

// ---------------- static problem configuration ----------------
#define TOTAL    6848
#define D_MODEL  768
#define D_INNER  1536
#define D_STATE  16
#define DT_RANK  48
#define NSUBJ    8
#define N_LAYERS 2
#define EPS      1e-5f

__constant__ int c_offsets[NSUBJ + 1] = {0, 1024, 1920, 2688, 3712, 4224, 4864, 5824, 6848};

#define IPW_N (2 * D_INNER * D_MODEL)
#define XPW_N ((DT_RANK + 2 * D_STATE) * D_INNER)
#define DTW_N (D_INNER * DT_RANK)
#define OPW_N (D_MODEL * D_INNER)

// ---------------- scratch (device globals; no runtime allocation) ----------------
__device__ float g_h  [TOTAL * D_MODEL];
__device__ float g_xz [TOTAL * 2 * D_INNER];
__device__ float g_xc [TOTAL * D_INNER];
__device__ float g_dbl[TOTAL * 80];
__device__ float g_dt [TOTAL * D_INNER];

__device__ __nv_bfloat16 g_hn_hi[TOTAL * D_MODEL],  g_hn_lo[TOTAL * D_MODEL];
__device__ __nv_bfloat16 g_xc_hi[TOTAL * D_INNER],  g_xc_lo[TOTAL * D_INNER];
__device__ __nv_bfloat16 g_db_hi[TOTAL * DT_RANK],  g_db_lo[TOTAL * DT_RANK];
__device__ __nv_bfloat16 g_y_hi [TOTAL * D_INNER],  g_y_lo [TOTAL * D_INNER];

__device__ __nv_bfloat16 g_ip_hi[N_LAYERS * IPW_N], g_ip_lo[N_LAYERS * IPW_N];
__device__ __nv_bfloat16 g_xp_hi[N_LAYERS * XPW_N], g_xp_lo[N_LAYERS * XPW_N];
__device__ __nv_bfloat16 g_dw_hi[N_LAYERS * DTW_N], g_dw_lo[N_LAYERS * DTW_N];
__device__ __nv_bfloat16 g_op_hi[N_LAYERS * OPW_N], g_op_lo[N_LAYERS * OPW_N];

// ---------------- helpers ----------------
__device__ __forceinline__ float blockReduceSum(float v) {
    __shared__ float sh[8];
    __shared__ float total;
    #pragma unroll
    for (int o = 16; o; o >>= 1) v += __shfl_xor_sync(0xffffffffu, v, o);
    if ((threadIdx.x & 31) == 0) sh[threadIdx.x >> 5] = v;
    __syncthreads();
    v = (threadIdx.x < 8) ? sh[threadIdx.x] : 0.f;
    #pragma unroll
    for (int o = 4; o; o >>= 1) v += __shfl_xor_sync(0xffffffffu, v, o);
    if (threadIdx.x == 0) total = v;
    __syncthreads();
    return total;
}

__device__ __forceinline__ float silu_f(float x) { return x / (1.f + __expf(-x)); }

__device__ __forceinline__ void split2v(float f0, float f1,
                                        __nv_bfloat162& hi, __nv_bfloat162& lo) {
    hi = __floats2bfloat162_rn(f0, f1);
    lo = __floats2bfloat162_rn(f0 - __bfloat162float(hi.x), f1 - __bfloat162float(hi.y));
}

__device__ __forceinline__ void mma_bf16(float* c, const uint32_t* a, uint32_t b0, uint32_t b1) {
    asm volatile(
        "mma.sync.aligned.m16n8k16.row.col.f32.bf16.bf16.f32 "
        "{%0,%1,%2,%3}, {%4,%5,%6,%7}, {%8,%9}, {%0,%1,%2,%3};"
        : "+f"(c[0]), "+f"(c[1]), "+f"(c[2]), "+f"(c[3])
        : "r"(a[0]), "r"(a[1]), "r"(a[2]), "r"(a[3]), "r"(b0), "r"(b1));
}

__device__ __forceinline__ void ldsm4(uint32_t* r, uint32_t addr) {
    asm volatile("ldmatrix.sync.aligned.m8n8.x4.shared.b16 {%0,%1,%2,%3}, [%4];"
        : "=r"(r[0]), "=r"(r[1]), "=r"(r[2]), "=r"(r[3]) : "r"(addr));
}

__device__ __forceinline__ void cp16(uint32_t dst, const void* src, int sz) {
    asm volatile("cp.async.cg.shared.global [%0], [%1], 16, %2;"
                 :: "r"(dst), "l"(src), "r"(sz));
}
#define CP_COMMIT() asm volatile("cp.async.commit_group;")
#define CP_WAIT(n)  asm volatile("cp.async.wait_group %0;" :: "n"(n))

// swizzled smem byte offset inside one 128x32 bf16 tile (64B rows)
__device__ __forceinline__ uint32_t sw_off(int row, int chunk) {
    return (uint32_t)(row * 64 + ((chunk ^ ((row >> 1) & 3)) << 4));
}

// ---------------- weight / activation split kernels ----------------
__global__ void __launch_bounds__(256) split_kernel(
    const float* __restrict__ src, __nv_bfloat16* __restrict__ hi,
    __nv_bfloat16* __restrict__ lo, int n4)
{
    int i = blockIdx.x * 256 + threadIdx.x;
    if (i >= n4) return;
    float4 v = ((const float4*)src)[i];
    __nv_bfloat162 h0, l0, h1, l1;
    split2v(v.x, v.y, h0, l0);
    split2v(v.z, v.w, h1, l1);
    ((__nv_bfloat162*)hi)[i * 2]     = h0;
    ((__nv_bfloat162*)hi)[i * 2 + 1] = h1;
    ((__nv_bfloat162*)lo)[i * 2]     = l0;
    ((__nv_bfloat162*)lo)[i * 2 + 1] = l1;
}

__global__ void __launch_bounds__(256) split48_kernel(
    const float* __restrict__ src, __nv_bfloat16* __restrict__ hi,
    __nv_bfloat16* __restrict__ lo)
{
    int p = blockIdx.x * 256 + threadIdx.x;
    if (p >= TOTAL * 24) return;
    int row = p / 24, cp = p % 24;
    const float* s = src + (size_t)row * 80 + cp * 2;
    __nv_bfloat162 h, l;
    split2v(s[0], s[1], h, l);
    ((__nv_bfloat162*)hi)[row * 24 + cp] = h;
    ((__nv_bfloat162*)lo)[row * 24 + cp] = l;
}

// ---------------- embed gather + rmsnorm (fp32 residual) ----------------
__global__ void __launch_bounds__(256) embed_rms_kernel(
    const int* __restrict__ tokens, const float* __restrict__ embed,
    const float* __restrict__ w, float* __restrict__ out)
{
    const int row = blockIdx.x;
    const float* xr = embed + (size_t)tokens[row] * D_MODEL;
    float s = 0.f;
    for (int i = threadIdx.x; i < D_MODEL; i += 256) { float v = xr[i]; s += v * v; }
    float tot = blockReduceSum(s);
    float r = rsqrtf(tot / D_MODEL + EPS);
    for (int i = threadIdx.x; i < D_MODEL; i += 256)
        out[row * D_MODEL + i] = xr[i] * r * w[i];
}

// ---------------- rmsnorm -> bf16 hi/lo ----------------
__global__ void __launch_bounds__(256) rms_split_kernel(
    const float* __restrict__ x, const float* __restrict__ w,
    __nv_bfloat16* __restrict__ hi, __nv_bfloat16* __restrict__ lo)
{
    const int row = blockIdx.x;
    const float* xr = x + row * D_MODEL;
    float s = 0.f;
    for (int i = threadIdx.x; i < D_MODEL; i += 256) { float v = xr[i]; s += v * v; }
    float tot = blockReduceSum(s);
    float r = rsqrtf(tot / D_MODEL + EPS);
    for (int p = threadIdx.x; p < D_MODEL / 2; p += 256) {
        float2 v = ((const float2*)xr)[p];
        float a = v.x * r * w[p * 2], b = v.y * r * w[p * 2 + 1];
        __nv_bfloat162 h, l;
        split2v(a, b, h, l);
        ((__nv_bfloat162*)hi)[row * (D_MODEL / 2) + p] = h;
        ((__nv_bfloat162*)lo)[row * (D_MODEL / 2) + p] = l;
    }
}

// ---------------- final: rmsnorm(norm_f) then rmsnorm(out_norm) ----------------
__global__ void __launch_bounds__(256) final_kernel(
    const float* __restrict__ x, const float* __restrict__ wf,
    const float* __restrict__ wo, float* __restrict__ out)
{
    const int row = blockIdx.x;
    const float* xr = x + row * D_MODEL;
    float s1 = 0.f, s2 = 0.f;
    for (int i = threadIdx.x; i < D_MODEL; i += 256) {
        float v = xr[i];
        float vw = v * wf[i];
        s1 += v * v;
        s2 += vw * vw;
    }
    float t1 = blockReduceSum(s1);
    float t2 = blockReduceSum(s2);
    float r1 = rsqrtf(t1 / D_MODEL + EPS);
    float m2 = (r1 * r1) * t2 / D_MODEL;
    float r2 = rsqrtf(m2 + EPS);
    for (int i = threadIdx.x; i < D_MODEL; i += 256)
        out[row * D_MODEL + i] = xr[i] * wf[i] * r1 * r2 * wo[i];
}

// ---------------- tensor-core GEMM (legacy mma.sync, split-bf16 3-term) ----------
// C[M,N] (op)= A[M,K] * W[N,K]^T, operands pre-split bf16 hi/lo.
// Block 128x128, 256 threads (8 warps, warp tile 64x32), BK=32,
// 3-stage cp.async ring, ldmatrix fragments, XOR-swizzled smem,
// term-major mma order (reuse distance 4 per accumulator).
// epi: 0 = store, 1 = softplus(acc + bias[n]), 2 = C += acc
#define GS_STAGE 32768
#define GS_A_HI  0
#define GS_A_LO  8192
#define GS_B_HI  16384
#define GS_B_LO  24576
#define GSMEM    (3 * GS_STAGE)

__device__ __forceinline__ void gemm_load_stage(
    uint32_t sb, int tid, int m0, int n0, int k0, int M, int N, int K,
    const __nv_bfloat16* __restrict__ Ah, const __nv_bfloat16* __restrict__ Al,
    const __nv_bfloat16* __restrict__ Wh, const __nv_bfloat16* __restrict__ Wl)
{
    #pragma unroll
    for (int half = 0; half < 2; half++) {
        int li = half * 256 + tid;          // 0..511
        int row = li >> 2, c = li & 3;
        int k = k0 + c * 8;
        int kin = (k < K) ? 16 : 0;
        int kc  = (k < K) ? k : 0;
        uint32_t off = sw_off(row, c);

        int ar = m0 + row; if (ar >= M) ar = M - 1;
        size_t ao = (size_t)ar * K + kc;
        cp16(sb + GS_A_HI + off, Ah + ao, kin);
        cp16(sb + GS_A_LO + off, Al + ao, kin);

        int br = n0 + row;
        int bin = (br < N) ? kin : 0;
        int brc = (br < N) ? br : 0;
        size_t bo = (size_t)brc * K + kc;
        cp16(sb + GS_B_HI + off, Wh + bo, bin);
        cp16(sb + GS_B_LO + off, Wl + bo, bin);
    }
}

__global__ void __launch_bounds__(256) gemm_tc_kernel(
    const __nv_bfloat16* __restrict__ Ah, const __nv_bfloat16* __restrict__ Al,
    const __nv_bfloat16* __restrict__ Wh, const __nv_bfloat16* __restrict__ Wl,
    const float* __restrict__ bias, float* __restrict__ C,
    int M, int N, int K, int epi)
{
    extern __shared__ uint8_t smem[];
    const int tid = threadIdx.x, lane = tid & 31, warp = tid >> 5;
    const int m0 = blockIdx.y * 128, n0 = blockIdx.x * 128;
    const int wm = (warp & 1) * 64, wn = (warp >> 1) * 32;
    const int g = lane >> 2, tg = lane & 3;

    uint32_t sbase = (uint32_t)__cvta_generic_to_shared(smem);

    float acc[4][4][4];
    #pragma unroll
    for (int mi = 0; mi < 4; mi++)
        #pragma unroll
        for (int ni = 0; ni < 4; ni++)
            #pragma unroll
            for (int r = 0; r < 4; r++) acc[mi][ni][r] = 0.f;

    const int KT = (K + 31) >> 5;
    // prologue: prefetch tiles 0 and 1 (two commit groups)
    gemm_load_stage(sbase, tid, m0, n0, 0, M, N, K, Ah, Al, Wh, Wl);
    CP_COMMIT();
    if (KT > 1) {
        gemm_load_stage(sbase + GS_STAGE, tid, m0, n0, 32, M, N, K, Ah, Al, Wh, Wl);
    }
    CP_COMMIT();

    const int mat = lane >> 3, mr = lane & 7;

    for (int kt = 0; kt < KT; kt++) {
        CP_WAIT(1);            // tile kt resident (kt+1's group may be pending)
        __syncthreads();       // also: all warps done computing tile kt-1

        if (kt + 2 < KT) {
            int st = kt + 2;
            gemm_load_stage(sbase + (st % 3) * GS_STAGE, tid, m0, n0,
                            st * 32, M, N, K, Ah, Al, Wh, Wl);
        }
        CP_COMMIT();

        uint32_t stb  = sbase + (kt % 3) * GS_STAGE;
        uint32_t Ah_b = stb + GS_A_HI, Al_b = stb + GS_A_LO;
        uint32_t Bh_b = stb + GS_B_HI, Bl_b = stb + GS_B_LO;

        #pragma unroll
        for (int s = 0; s < 2; s++) {
            // B fragments: two x4 per precision cover 4 n-groups (n8 each)
            uint32_t bh[4][2], bl[4][2];
            #pragma unroll
            for (int pair = 0; pair < 2; pair++) {
                int nrow = wn + pair * 16 + ((mat >> 1) << 3) + mr;
                int chunk = s * 2 + (mat & 1);
                uint32_t off = sw_off(nrow, chunk);
                uint32_t r[4];
                ldsm4(r, Bh_b + off);
                bh[pair * 2][0] = r[0]; bh[pair * 2][1] = r[1];
                bh[pair * 2 + 1][0] = r[2]; bh[pair * 2 + 1][1] = r[3];
                ldsm4(r, Bl_b + off);
                bl[pair * 2][0] = r[0]; bl[pair * 2][1] = r[1];
                bl[pair * 2 + 1][0] = r[2]; bl[pair * 2 + 1][1] = r[3];
            }
            #pragma unroll
            for (int mi = 0; mi < 4; mi++) {
                int arow = wm + mi * 16 + ((mat & 1) << 3) + mr;
                int chunk = s * 2 + (mat >> 1);
                uint32_t off = sw_off(arow, chunk);
                uint32_t ah[4], al[4];
                ldsm4(ah, Ah_b + off);
                ldsm4(al, Al_b + off);
                // term-major: reuse distance 4 per accumulator
                #pragma unroll
                for (int ni = 0; ni < 4; ni++) mma_bf16(acc[mi][ni], ah, bh[ni][0], bh[ni][1]);
                #pragma unroll
                for (int ni = 0; ni < 4; ni++) mma_bf16(acc[mi][ni], ah, bl[ni][0], bl[ni][1]);
                #pragma unroll
                for (int ni = 0; ni < 4; ni++) mma_bf16(acc[mi][ni], al, bh[ni][0], bh[ni][1]);
            }
        }
    }

    // ---- epilogue ----
    #pragma unroll
    for (int mi = 0; mi < 4; mi++) {
        int mrow0 = m0 + wm + mi * 16 + g;
        int mrow1 = mrow0 + 8;
        #pragma unroll
        for (int ni = 0; ni < 4; ni++) {
            int n = n0 + wn + ni * 8 + 2 * tg;
            if (n >= N) continue;   // N multiple of 8 -> pair-safe
            float* c = acc[mi][ni];
            if (epi == 1) {
                float b0 = bias[n], b1 = bias[n + 1];
                #pragma unroll
                for (int r = 0; r < 4; r++) {
                    float v = c[r] + ((r & 1) ? b1 : b0);
                    c[r] = (v > 20.f) ? v : log1pf(__expf(v));
                }
            }
            if (mrow0 < M) {
                size_t b = (size_t)mrow0 * N + n;
                if (epi == 2) { C[b] += c[0]; C[b + 1] += c[1]; }
                else          { C[b]  = c[0]; C[b + 1]  = c[1]; }
            }
            if (mrow1 < M) {
                size_t b = (size_t)mrow1 * N + n;
                if (epi == 2) { C[b] += c[2]; C[b + 1] += c[3]; }
                else          { C[b]  = c[2]; C[b + 1]  = c[3]; }
            }
        }
    }
}

// ---------------- causal depthwise conv (k=4) + bias + silu (+ split) ----------------
__global__ void __launch_bounds__(256) conv_kernel(
    const float* __restrict__ xz, const float* __restrict__ cw,
    const float* __restrict__ cb, float* __restrict__ xc,
    __nv_bfloat16* __restrict__ xc_hi, __nv_bfloat16* __restrict__ xc_lo)
{
    int p = blockIdx.x * 256 + threadIdx.x;
    if (p >= TOTAL * (D_INNER / 2)) return;
    int t = p / (D_INNER / 2);
    int i = (p - t * (D_INNER / 2)) * 2;
    int t0 = 0;
    #pragma unroll
    for (int s = 1; s < NSUBJ; s++)
        if (t >= c_offsets[s]) t0 = c_offsets[s];

    float o[2];
    #pragma unroll
    for (int u = 0; u < 2; u++) {
        int ch = i + u;
        float w0 = cw[ch * 4 + 0], w1 = cw[ch * 4 + 1], w2 = cw[ch * 4 + 2], w3 = cw[ch * 4 + 3];
        float acc = cb[ch] + w3 * xz[(size_t)t * (2 * D_INNER) + ch];
        if (t - 1 >= t0) acc = fmaf(w2, xz[(size_t)(t - 1) * (2 * D_INNER) + ch], acc);
        if (t - 2 >= t0) acc = fmaf(w1, xz[(size_t)(t - 2) * (2 * D_INNER) + ch], acc);
        if (t - 3 >= t0) acc = fmaf(w0, xz[(size_t)(t - 3) * (2 * D_INNER) + ch], acc);
        o[u] = silu_f(acc);
    }
    ((float2*)xc)[p] = make_float2(o[0], o[1]);
    __nv_bfloat162 h, l;
    split2v(o[0], o[1], h, l);
    ((__nv_bfloat162*)xc_hi)[p] = h;
    ((__nv_bfloat162*)xc_lo)[p] = l;
}

// ---------------- selective scan (+ D skip + silu(z) gate), split output ----------------
__global__ void __launch_bounds__(256) scan_kernel(
    const float* __restrict__ xc, const float* __restrict__ dt,
    const float* __restrict__ dbl, const float* __restrict__ xz,
    const float* __restrict__ A_log, const float* __restrict__ Dp,
    __nv_bfloat16* __restrict__ y_hi, __nv_bfloat16* __restrict__ y_lo)
{
    const int subj = blockIdx.y;
    const int d0 = blockIdx.x * 16;
    const int off = c_offsets[subj];
    const int L = c_offsets[subj + 1] - off;
    const int tid = threadIdx.x;
    const int dl = tid >> 4;
    const int n  = tid & 15;
    const int d  = d0 + dl;

    const float Acoef = -__expf(A_log[d * D_STATE + n]);
    const float Dv = Dp[d];
    float hc = 0.f;

    __shared__ float sh_dt[64][16], sh_x[64][16], sh_z[64][16], sh_B[64][16], sh_C[64][16];

    for (int tb = 0; tb < L; tb += 64) {
        int nsteps = min(64, L - tb);
        for (int idx = tid; idx < 64 * 16; idx += 256) {
            int tl = idx >> 4, dd = idx & 15;
            if (tl < nsteps) {
                int t = off + tb + tl;
                sh_dt[tl][dd] = dt[(size_t)t * D_INNER + d0 + dd];
                sh_x [tl][dd] = xc[(size_t)t * D_INNER + d0 + dd];
                sh_z [tl][dd] = xz[(size_t)t * (2 * D_INNER) + D_INNER + d0 + dd];
                sh_B [tl][dd] = dbl[(size_t)t * 80 + DT_RANK + dd];
                sh_C [tl][dd] = dbl[(size_t)t * 80 + DT_RANK + D_STATE + dd];
            }
        }
        __syncthreads();
        for (int s = 0; s < nsteps; s++) {
            float dtv = sh_dt[s][dl];
            float xv  = sh_x[s][dl];
            float dA = __expf(dtv * Acoef);
            hc = fmaf(dA, hc, (dtv * xv) * sh_B[s][n]);
            float p = hc * sh_C[s][n];
            p += __shfl_xor_sync(0xffffffffu, p, 1);
            p += __shfl_xor_sync(0xffffffffu, p, 2);
            p += __shfl_xor_sync(0xffffffffu, p, 4);
            p += __shfl_xor_sync(0xffffffffu, p, 8);
            if (n == 0) {
                float yv = p + xv * Dv;
                yv *= silu_f(sh_z[s][dl]);
                __nv_bfloat16 h = __float2bfloat16_rn(yv);
                __nv_bfloat16 l = __float2bfloat16_rn(yv - __bfloat162float(h));
                size_t o = (size_t)(off + tb + s) * D_INNER + d;
                y_hi[o] = h;
                y_lo[o] = l;
            }
        }
        __syncthreads();
    }
}

// ---------------- launch ----------------
extern "C" void kernel_launch(void* const* d_in, const int* in_sizes, int n_in,
                              void* d_out, int out_size) {
    const int*   tokens     = (const int*)  d_in[0];
    const float* embed      = (const float*)d_in[1];
    const float* in_norm_w  = (const float*)d_in[2];
    const float* out_norm_w = (const float*)d_in[3];
    const float* norm_w     = (const float*)d_in[4];
    const float* in_proj_w  = (const float*)d_in[5];
    const float* conv_w     = (const float*)d_in[6];
    const float* conv_b     = (const float*)d_in[7];
    const float* x_proj_w   = (const float*)d_in[8];
    const float* dt_proj_w  = (const float*)d_in[9];
    const float* dt_proj_b  = (const float*)d_in[10];
    const float* A_log      = (const float*)d_in[11];
    const float* D_param    = (const float*)d_in[12];
    const float* out_proj_w = (const float*)d_in[13];
    const float* norm_f_w   = (const float*)d_in[14];
    float* out = (float*)d_out;

    float *h, *xz, *xc, *dbl, *dt;
    __nv_bfloat16 *hn_hi, *hn_lo, *xc_hi, *xc_lo, *db_hi, *db_lo, *y_hi, *y_lo;
    __nv_bfloat16 *ip_hi, *ip_lo, *xp_hi, *xp_lo, *dw_hi, *dw_lo, *op_hi, *op_lo;
    cudaGetSymbolAddress((void**)&h,   g_h);
    cudaGetSymbolAddress((void**)&xz,  g_xz);
    cudaGetSymbolAddress((void**)&xc,  g_xc);
    cudaGetSymbolAddress((void**)&dbl, g_dbl);
    cudaGetSymbolAddress((void**)&dt,  g_dt);
    cudaGetSymbolAddress((void**)&hn_hi, g_hn_hi); cudaGetSymbolAddress((void**)&hn_lo, g_hn_lo);
    cudaGetSymbolAddress((void**)&xc_hi, g_xc_hi); cudaGetSymbolAddress((void**)&xc_lo, g_xc_lo);
    cudaGetSymbolAddress((void**)&db_hi, g_db_hi); cudaGetSymbolAddress((void**)&db_lo, g_db_lo);
    cudaGetSymbolAddress((void**)&y_hi,  g_y_hi);  cudaGetSymbolAddress((void**)&y_lo,  g_y_lo);
    cudaGetSymbolAddress((void**)&ip_hi, g_ip_hi); cudaGetSymbolAddress((void**)&ip_lo, g_ip_lo);
    cudaGetSymbolAddress((void**)&xp_hi, g_xp_hi); cudaGetSymbolAddress((void**)&xp_lo, g_xp_lo);
    cudaGetSymbolAddress((void**)&dw_hi, g_dw_hi); cudaGetSymbolAddress((void**)&dw_lo, g_dw_lo);
    cudaGetSymbolAddress((void**)&op_hi, g_op_hi); cudaGetSymbolAddress((void**)&op_lo, g_op_lo);

    cudaFuncSetAttribute(gemm_tc_kernel, cudaFuncAttributeMaxDynamicSharedMemorySize, GSMEM);

    const int MB = (TOTAL + 127) / 128;   // 54

    // one-time per launch: split all weights to bf16 hi/lo
    split_kernel<<<(N_LAYERS * IPW_N / 4 + 255) / 256, 256>>>(in_proj_w,  ip_hi, ip_lo, N_LAYERS * IPW_N / 4);
    split_kernel<<<(N_LAYERS * XPW_N / 4 + 255) / 256, 256>>>(x_proj_w,   xp_hi, xp_lo, N_LAYERS * XPW_N / 4);
    split_kernel<<<(N_LAYERS * DTW_N / 4 + 255) / 256, 256>>>(dt_proj_w,  dw_hi, dw_lo, N_LAYERS * DTW_N / 4);
    split_kernel<<<(N_LAYERS * OPW_N / 4 + 255) / 256, 256>>>(out_proj_w, op_hi, op_lo, N_LAYERS * OPW_N / 4);

    embed_rms_kernel<<<TOTAL, 256>>>(tokens, embed, in_norm_w, h);

    for (int l = 0; l < N_LAYERS; l++) {
        rms_split_kernel<<<TOTAL, 256>>>(h, norm_w + l * D_MODEL, hn_hi, hn_lo);

        // xz = hn @ in_proj_w^T   [TOTAL, 3072]
        gemm_tc_kernel<<<dim3(2 * D_INNER / 128, MB), 256, GSMEM>>>(
            hn_hi, hn_lo, ip_hi + (size_t)l * IPW_N, ip_lo + (size_t)l * IPW_N,
            nullptr, xz, TOTAL, 2 * D_INNER, D_MODEL, 0);

        conv_kernel<<<(TOTAL * D_INNER / 2 + 255) / 256, 256>>>(
            xz, conv_w + (size_t)l * D_INNER * 4, conv_b + (size_t)l * D_INNER,
            xc, xc_hi, xc_lo);

        // dbl = xc @ x_proj_w^T   [TOTAL, 80]
        gemm_tc_kernel<<<dim3(1, MB), 256, GSMEM>>>(
            xc_hi, xc_lo, xp_hi + (size_t)l * XPW_N, xp_lo + (size_t)l * XPW_N,
            nullptr, dbl, TOTAL, 80, D_INNER, 0);

        split48_kernel<<<(TOTAL * 24 + 255) / 256, 256>>>(dbl, db_hi, db_lo);

        // dt = softplus(dbl[:, :48] @ dt_proj_w^T + b)   [TOTAL, 1536]
        gemm_tc_kernel<<<dim3(D_INNER / 128, MB), 256, GSMEM>>>(
            db_hi, db_lo, dw_hi + (size_t)l * DTW_N, dw_lo + (size_t)l * DTW_N,
            dt_proj_b + (size_t)l * D_INNER, dt, TOTAL, D_INNER, DT_RANK, 1);

        scan_kernel<<<dim3(D_INNER / 16, NSUBJ), 256>>>(
            xc, dt, dbl, xz,
            A_log + (size_t)l * D_INNER * D_STATE, D_param + (size_t)l * D_INNER,
            y_hi, y_lo);

        // h += y @ out_proj_w^T   [TOTAL, 768]
        gemm_tc_kernel<<<dim3(D_MODEL / 128, MB), 256, GSMEM>>>(
            y_hi, y_lo, op_hi + (size_t)l * OPW_N, op_lo + (size_t)l * OPW_N,
            nullptr, h, TOTAL, D_MODEL, D_INNER, 2);
    }

    final_kernel<<<TOTAL, 256>>>(h, norm_f_w, out_norm_w, out);
}

// round 15
// speedup vs baseline: 1.1577x; 1.0920x over previous
#include <cuda_runtime.h>
#include <cuda_bf16.h>
#include <cstdint>

// ---------------- static problem configuration ----------------
#define TOTAL    6848
#define D_MODEL  768
#define D_INNER  1536
#define D_STATE  16
#define DT_RANK  48
#define NSUBJ    8
#define N_LAYERS 2
#define EPS      1e-5f

__constant__ int c_offsets[NSUBJ + 1] = {0, 1024, 1920, 2688, 3712, 4224, 4864, 5824, 6848};

#define IPW_N (2 * D_INNER * D_MODEL)
#define XPW_N ((DT_RANK + 2 * D_STATE) * D_INNER)
#define DTW_N (D_INNER * DT_RANK)
#define OPW_N (D_MODEL * D_INNER)

// ---------------- scratch (device globals; no runtime allocation) ----------------
__device__ float g_h  [TOTAL * D_MODEL];
__device__ float g_xz [TOTAL * 2 * D_INNER];
__device__ float g_xc [TOTAL * D_INNER];
__device__ float g_dbl[TOTAL * 80];
__device__ float g_dt [TOTAL * D_INNER];

__device__ __nv_bfloat16 g_hn_hi[TOTAL * D_MODEL],  g_hn_lo[TOTAL * D_MODEL];
__device__ __nv_bfloat16 g_xc_hi[TOTAL * D_INNER],  g_xc_lo[TOTAL * D_INNER];
__device__ __nv_bfloat16 g_db_hi[TOTAL * DT_RANK],  g_db_lo[TOTAL * DT_RANK];
__device__ __nv_bfloat16 g_y_hi [TOTAL * D_INNER],  g_y_lo [TOTAL * D_INNER];

__device__ __nv_bfloat16 g_ip_hi[N_LAYERS * IPW_N], g_ip_lo[N_LAYERS * IPW_N];
__device__ __nv_bfloat16 g_xp_hi[N_LAYERS * XPW_N], g_xp_lo[N_LAYERS * XPW_N];
__device__ __nv_bfloat16 g_dw_hi[N_LAYERS * DTW_N], g_dw_lo[N_LAYERS * DTW_N];
__device__ __nv_bfloat16 g_op_hi[N_LAYERS * OPW_N], g_op_lo[N_LAYERS * OPW_N];

// ---------------- helpers ----------------
__device__ __forceinline__ float blockReduceSum(float v) {
    __shared__ float sh[8];
    __shared__ float total;
    #pragma unroll
    for (int o = 16; o; o >>= 1) v += __shfl_xor_sync(0xffffffffu, v, o);
    if ((threadIdx.x & 31) == 0) sh[threadIdx.x >> 5] = v;
    __syncthreads();
    v = (threadIdx.x < 8) ? sh[threadIdx.x] : 0.f;
    #pragma unroll
    for (int o = 4; o; o >>= 1) v += __shfl_xor_sync(0xffffffffu, v, o);
    if (threadIdx.x == 0) total = v;
    __syncthreads();
    return total;
}

__device__ __forceinline__ float silu_f(float x) { return x / (1.f + __expf(-x)); }

__device__ __forceinline__ void split2v(float f0, float f1,
                                        __nv_bfloat162& hi, __nv_bfloat162& lo) {
    hi = __floats2bfloat162_rn(f0, f1);
    lo = __floats2bfloat162_rn(f0 - __bfloat162float(hi.x), f1 - __bfloat162float(hi.y));
}

__device__ __forceinline__ void mma_bf16(float* c, const uint32_t* a, uint32_t b0, uint32_t b1) {
    asm volatile(
        "mma.sync.aligned.m16n8k16.row.col.f32.bf16.bf16.f32 "
        "{%0,%1,%2,%3}, {%4,%5,%6,%7}, {%8,%9}, {%0,%1,%2,%3};"
        : "+f"(c[0]), "+f"(c[1]), "+f"(c[2]), "+f"(c[3])
        : "r"(a[0]), "r"(a[1]), "r"(a[2]), "r"(a[3]), "r"(b0), "r"(b1));
}

__device__ __forceinline__ void ldsm4(uint32_t* r, uint32_t addr) {
    asm volatile("ldmatrix.sync.aligned.m8n8.x4.shared.b16 {%0,%1,%2,%3}, [%4];"
        : "=r"(r[0]), "=r"(r[1]), "=r"(r[2]), "=r"(r[3]) : "r"(addr));
}

__device__ __forceinline__ void cp16(uint32_t dst, const void* src, int sz) {
    asm volatile("cp.async.cg.shared.global [%0], [%1], 16, %2;"
                 :: "r"(dst), "l"(src), "r"(sz));
}
#define CP_COMMIT() asm volatile("cp.async.commit_group;")
#define CP_WAIT(n)  asm volatile("cp.async.wait_group %0;" :: "n"(n))

// swizzled smem byte offset inside one 128x32 bf16 tile (64B rows)
__device__ __forceinline__ uint32_t sw_off(int row, int chunk) {
    return (uint32_t)(row * 64 + ((chunk ^ ((row >> 1) & 3)) << 4));
}

// ---------------- weight split kernels ----------------
__global__ void __launch_bounds__(256) split_kernel(
    const float* __restrict__ src, __nv_bfloat16* __restrict__ hi,
    __nv_bfloat16* __restrict__ lo, int n4)
{
    int i = blockIdx.x * 256 + threadIdx.x;
    if (i >= n4) return;
    float4 v = ((const float4*)src)[i];
    __nv_bfloat162 h0, l0, h1, l1;
    split2v(v.x, v.y, h0, l0);
    split2v(v.z, v.w, h1, l1);
    ((__nv_bfloat162*)hi)[i * 2]     = h0;
    ((__nv_bfloat162*)hi)[i * 2 + 1] = h1;
    ((__nv_bfloat162*)lo)[i * 2]     = l0;
    ((__nv_bfloat162*)lo)[i * 2 + 1] = l1;
}

// ---------------- embed gather + rmsnorm(in_norm) + rmsnorm(norm_w0) + split ----------
__global__ void __launch_bounds__(256) embed_fused_kernel(
    const int* __restrict__ tokens, const float* __restrict__ embed,
    const float* __restrict__ w_in, const float* __restrict__ w_n0,
    float* __restrict__ hout,
    __nv_bfloat16* __restrict__ hi, __nv_bfloat16* __restrict__ lo)
{
    const int row = blockIdx.x;
    const float* xr = embed + (size_t)tokens[row] * D_MODEL;
    float xv[3];
    float s1 = 0.f;
    #pragma unroll
    for (int j = 0; j < 3; j++) {
        int i = threadIdx.x + j * 256;
        float v = xr[i];
        xv[j] = v;
        s1 += v * v;
    }
    float t1 = blockReduceSum(s1);
    float r1 = rsqrtf(t1 / D_MODEL + EPS);
    float hv[3];
    float s2 = 0.f;
    #pragma unroll
    for (int j = 0; j < 3; j++) {
        int i = threadIdx.x + j * 256;
        float v = xv[j] * r1 * w_in[i];
        hv[j] = v;
        hout[row * D_MODEL + i] = v;
        s2 += v * v;
    }
    float t2 = blockReduceSum(s2);
    float r2 = rsqrtf(t2 / D_MODEL + EPS);
    #pragma unroll
    for (int j = 0; j < 3; j++) {
        int i = threadIdx.x + j * 256;
        float v = hv[j] * r2 * w_n0[i];
        __nv_bfloat16 hb = __float2bfloat16_rn(v);
        __nv_bfloat16 lb = __float2bfloat16_rn(v - __bfloat162float(hb));
        hi[row * D_MODEL + i] = hb;
        lo[row * D_MODEL + i] = lb;
    }
}

// ---------------- rmsnorm -> bf16 hi/lo ----------------
__global__ void __launch_bounds__(256) rms_split_kernel(
    const float* __restrict__ x, const float* __restrict__ w,
    __nv_bfloat16* __restrict__ hi, __nv_bfloat16* __restrict__ lo)
{
    const int row = blockIdx.x;
    const float* xr = x + row * D_MODEL;
    float s = 0.f;
    for (int i = threadIdx.x; i < D_MODEL; i += 256) { float v = xr[i]; s += v * v; }
    float tot = blockReduceSum(s);
    float r = rsqrtf(tot / D_MODEL + EPS);
    for (int p = threadIdx.x; p < D_MODEL / 2; p += 256) {
        float2 v = ((const float2*)xr)[p];
        float a = v.x * r * w[p * 2], b = v.y * r * w[p * 2 + 1];
        __nv_bfloat162 h, l;
        split2v(a, b, h, l);
        ((__nv_bfloat162*)hi)[row * (D_MODEL / 2) + p] = h;
        ((__nv_bfloat162*)lo)[row * (D_MODEL / 2) + p] = l;
    }
}

// ---------------- final: rmsnorm(norm_f) then rmsnorm(out_norm) ----------------
__global__ void __launch_bounds__(256) final_kernel(
    const float* __restrict__ x, const float* __restrict__ wf,
    const float* __restrict__ wo, float* __restrict__ out)
{
    const int row = blockIdx.x;
    const float* xr = x + row * D_MODEL;
    float s1 = 0.f, s2 = 0.f;
    for (int i = threadIdx.x; i < D_MODEL; i += 256) {
        float v = xr[i];
        float vw = v * wf[i];
        s1 += v * v;
        s2 += vw * vw;
    }
    float t1 = blockReduceSum(s1);
    float t2 = blockReduceSum(s2);
    float r1 = rsqrtf(t1 / D_MODEL + EPS);
    float m2 = (r1 * r1) * t2 / D_MODEL;
    float r2 = rsqrtf(m2 + EPS);
    for (int i = threadIdx.x; i < D_MODEL; i += 256)
        out[row * D_MODEL + i] = xr[i] * wf[i] * r1 * r2 * wo[i];
}

// ---------------- tensor-core GEMM (legacy mma.sync, split-bf16 3-term) ----------
// C[M,N] (op)= A[M,K] * W[N,K]^T, operands pre-split bf16 hi/lo.
// Block 128x128, 256 threads (8 warps, warp tile 64x32), BK=32,
// 2-stage cp.async double buffer (exact R4 structure), forced 2 CTAs/SM.
// epi: 0 = store, 1 = softplus(acc + bias[n]), 2 = C += acc,
//      3 = store + split cols [0,48) to ehi/elo (compact lda 48)
#define GS_STAGE 32768
#define GS_A_HI  0
#define GS_A_LO  8192
#define GS_B_HI  16384
#define GS_B_LO  24576
#define GSMEM    (2 * GS_STAGE)

__device__ __forceinline__ void gemm_load_stage(
    uint32_t sb, int tid, int m0, int n0, int k0, int M, int N, int K,
    const __nv_bfloat16* __restrict__ Ah, const __nv_bfloat16* __restrict__ Al,
    const __nv_bfloat16* __restrict__ Wh, const __nv_bfloat16* __restrict__ Wl)
{
    #pragma unroll
    for (int half = 0; half < 2; half++) {
        int li = half * 256 + tid;          // 0..511
        int row = li >> 2, c = li & 3;
        int k = k0 + c * 8;
        int kin = (k < K) ? 16 : 0;
        int kc  = (k < K) ? k : 0;
        uint32_t off = sw_off(row, c);

        int ar = m0 + row; if (ar >= M) ar = M - 1;
        size_t ao = (size_t)ar * K + kc;
        cp16(sb + GS_A_HI + off, Ah + ao, kin);
        cp16(sb + GS_A_LO + off, Al + ao, kin);

        int br = n0 + row;
        int bin = (br < N) ? kin : 0;
        int brc = (br < N) ? br : 0;
        size_t bo = (size_t)brc * K + kc;
        cp16(sb + GS_B_HI + off, Wh + bo, bin);
        cp16(sb + GS_B_LO + off, Wl + bo, bin);
    }
}

__global__ void __launch_bounds__(256, 2) gemm_tc_kernel(
    const __nv_bfloat16* __restrict__ Ah, const __nv_bfloat16* __restrict__ Al,
    const __nv_bfloat16* __restrict__ Wh, const __nv_bfloat16* __restrict__ Wl,
    const float* __restrict__ bias, float* __restrict__ C,
    __nv_bfloat16* __restrict__ ehi, __nv_bfloat16* __restrict__ elo,
    int M, int N, int K, int epi)
{
    extern __shared__ uint8_t smem[];
    const int tid = threadIdx.x, lane = tid & 31, warp = tid >> 5;
    const int m0 = blockIdx.y * 128, n0 = blockIdx.x * 128;
    const int wm = (warp & 1) * 64, wn = (warp >> 1) * 32;
    const int g = lane >> 2, tg = lane & 3;

    uint32_t sbase = (uint32_t)__cvta_generic_to_shared(smem);

    float acc[4][4][4];
    #pragma unroll
    for (int mi = 0; mi < 4; mi++)
        #pragma unroll
        for (int ni = 0; ni < 4; ni++)
            #pragma unroll
            for (int r = 0; r < 4; r++) acc[mi][ni][r] = 0.f;

    const int KT = (K + 31) >> 5;
    gemm_load_stage(sbase, tid, m0, n0, 0, M, N, K, Ah, Al, Wh, Wl);
    CP_COMMIT();

    const int mat = lane >> 3, mr = lane & 7;

    for (int kt = 0; kt < KT; kt++) {
        if (kt + 1 < KT) {
            gemm_load_stage(sbase + ((kt + 1) & 1) * GS_STAGE, tid, m0, n0,
                            (kt + 1) * 32, M, N, K, Ah, Al, Wh, Wl);
            CP_COMMIT();
            CP_WAIT(1);
        } else {
            CP_WAIT(0);
        }
        __syncthreads();

        uint32_t stb  = sbase + (kt & 1) * GS_STAGE;
        uint32_t Ah_b = stb + GS_A_HI, Al_b = stb + GS_A_LO;
        uint32_t Bh_b = stb + GS_B_HI, Bl_b = stb + GS_B_LO;

        #pragma unroll
        for (int s = 0; s < 2; s++) {
            uint32_t bh[4][2], bl[4][2];
            #pragma unroll
            for (int pair = 0; pair < 2; pair++) {
                int nrow = wn + pair * 16 + ((mat >> 1) << 3) + mr;
                int chunk = s * 2 + (mat & 1);
                uint32_t off = sw_off(nrow, chunk);
                uint32_t r[4];
                ldsm4(r, Bh_b + off);
                bh[pair * 2][0] = r[0]; bh[pair * 2][1] = r[1];
                bh[pair * 2 + 1][0] = r[2]; bh[pair * 2 + 1][1] = r[3];
                ldsm4(r, Bl_b + off);
                bl[pair * 2][0] = r[0]; bl[pair * 2][1] = r[1];
                bl[pair * 2 + 1][0] = r[2]; bl[pair * 2 + 1][1] = r[3];
            }
            #pragma unroll
            for (int mi = 0; mi < 4; mi++) {
                int arow = wm + mi * 16 + ((mat & 1) << 3) + mr;
                int chunk = s * 2 + (mat >> 1);
                uint32_t off = sw_off(arow, chunk);
                uint32_t ah[4], al[4];
                ldsm4(ah, Ah_b + off);
                ldsm4(al, Al_b + off);
                #pragma unroll
                for (int ni = 0; ni < 4; ni++) {
                    mma_bf16(acc[mi][ni], ah, bh[ni][0], bh[ni][1]);
                    mma_bf16(acc[mi][ni], ah, bl[ni][0], bl[ni][1]);
                    mma_bf16(acc[mi][ni], al, bh[ni][0], bh[ni][1]);
                }
            }
        }
        __syncthreads();
    }

    // ---- epilogue ----
    #pragma unroll
    for (int mi = 0; mi < 4; mi++) {
        int mrow0 = m0 + wm + mi * 16 + g;
        int mrow1 = mrow0 + 8;
        #pragma unroll
        for (int ni = 0; ni < 4; ni++) {
            int n = n0 + wn + ni * 8 + 2 * tg;
            if (n >= N) continue;   // N multiple of 8 -> pair-safe
            float* c = acc[mi][ni];
            if (epi == 1) {
                float b0 = bias[n], b1 = bias[n + 1];
                #pragma unroll
                for (int r = 0; r < 4; r++) {
                    float v = c[r] + ((r & 1) ? b1 : b0);
                    c[r] = (v > 20.f) ? v : log1pf(__expf(v));
                }
            }
            if (mrow0 < M) {
                size_t b = (size_t)mrow0 * N + n;
                if (epi == 2) { C[b] += c[0]; C[b + 1] += c[1]; }
                else          { C[b]  = c[0]; C[b + 1]  = c[1]; }
                if (epi == 3 && n < DT_RANK) {
                    __nv_bfloat162 h, l;
                    split2v(c[0], c[1], h, l);
                    ((__nv_bfloat162*)ehi)[mrow0 * (DT_RANK / 2) + (n >> 1)] = h;
                    ((__nv_bfloat162*)elo)[mrow0 * (DT_RANK / 2) + (n >> 1)] = l;
                }
            }
            if (mrow1 < M) {
                size_t b = (size_t)mrow1 * N + n;
                if (epi == 2) { C[b] += c[2]; C[b + 1] += c[3]; }
                else          { C[b]  = c[2]; C[b + 1]  = c[3]; }
                if (epi == 3 && n < DT_RANK) {
                    __nv_bfloat162 h, l;
                    split2v(c[2], c[3], h, l);
                    ((__nv_bfloat162*)ehi)[mrow1 * (DT_RANK / 2) + (n >> 1)] = h;
                    ((__nv_bfloat162*)elo)[mrow1 * (DT_RANK / 2) + (n >> 1)] = l;
                }
            }
        }
    }
}

// ---------------- causal depthwise conv (k=4) + bias + silu (+ split) ----------------
__global__ void __launch_bounds__(256) conv_kernel(
    const float* __restrict__ xz, const float* __restrict__ cw,
    const float* __restrict__ cb, float* __restrict__ xc,
    __nv_bfloat16* __restrict__ xc_hi, __nv_bfloat16* __restrict__ xc_lo)
{
    int p = blockIdx.x * 256 + threadIdx.x;
    if (p >= TOTAL * (D_INNER / 2)) return;
    int t = p / (D_INNER / 2);
    int i = (p - t * (D_INNER / 2)) * 2;
    int t0 = 0;
    #pragma unroll
    for (int s = 1; s < NSUBJ; s++)
        if (t >= c_offsets[s]) t0 = c_offsets[s];

    float o[2];
    #pragma unroll
    for (int u = 0; u < 2; u++) {
        int ch = i + u;
        float w0 = cw[ch * 4 + 0], w1 = cw[ch * 4 + 1], w2 = cw[ch * 4 + 2], w3 = cw[ch * 4 + 3];
        float acc = cb[ch] + w3 * xz[(size_t)t * (2 * D_INNER) + ch];
        if (t - 1 >= t0) acc = fmaf(w2, xz[(size_t)(t - 1) * (2 * D_INNER) + ch], acc);
        if (t - 2 >= t0) acc = fmaf(w1, xz[(size_t)(t - 2) * (2 * D_INNER) + ch], acc);
        if (t - 3 >= t0) acc = fmaf(w0, xz[(size_t)(t - 3) * (2 * D_INNER) + ch], acc);
        o[u] = silu_f(acc);
    }
    ((float2*)xc)[p] = make_float2(o[0], o[1]);
    __nv_bfloat162 h, l;
    split2v(o[0], o[1], h, l);
    ((__nv_bfloat162*)xc_hi)[p] = h;
    ((__nv_bfloat162*)xc_lo)[p] = l;
}

// ---------------- selective scan (+ D skip + silu(z) gate), split output ----------------
__global__ void __launch_bounds__(256) scan_kernel(
    const float* __restrict__ xc, const float* __restrict__ dt,
    const float* __restrict__ dbl, const float* __restrict__ xz,
    const float* __restrict__ A_log, const float* __restrict__ Dp,
    __nv_bfloat16* __restrict__ y_hi, __nv_bfloat16* __restrict__ y_lo)
{
    const int subj = blockIdx.y;
    const int d0 = blockIdx.x * 16;
    const int off = c_offsets[subj];
    const int L = c_offsets[subj + 1] - off;
    const int tid = threadIdx.x;
    const int dl = tid >> 4;
    const int n  = tid & 15;
    const int d  = d0 + dl;

    const float Acoef = -__expf(A_log[d * D_STATE + n]);
    const float Dv = Dp[d];
    float hc = 0.f;

    __shared__ float sh_dt[64][16], sh_x[64][16], sh_z[64][16], sh_B[64][16], sh_C[64][16];

    for (int tb = 0; tb < L; tb += 64) {
        int nsteps = min(64, L - tb);
        for (int idx = tid; idx < 64 * 16; idx += 256) {
            int tl = idx >> 4, dd = idx & 15;
            if (tl < nsteps) {
                int t = off + tb + tl;
                sh_dt[tl][dd] = dt[(size_t)t * D_INNER + d0 + dd];
                sh_x [tl][dd] = xc[(size_t)t * D_INNER + d0 + dd];
                sh_z [tl][dd] = xz[(size_t)t * (2 * D_INNER) + D_INNER + d0 + dd];
                sh_B [tl][dd] = dbl[(size_t)t * 80 + DT_RANK + dd];
                sh_C [tl][dd] = dbl[(size_t)t * 80 + DT_RANK + D_STATE + dd];
            }
        }
        __syncthreads();
        for (int s = 0; s < nsteps; s++) {
            float dtv = sh_dt[s][dl];
            float xv  = sh_x[s][dl];
            float dA = __expf(dtv * Acoef);
            hc = fmaf(dA, hc, (dtv * xv) * sh_B[s][n]);
            float p = hc * sh_C[s][n];
            p += __shfl_xor_sync(0xffffffffu, p, 1);
            p += __shfl_xor_sync(0xffffffffu, p, 2);
            p += __shfl_xor_sync(0xffffffffu, p, 4);
            p += __shfl_xor_sync(0xffffffffu, p, 8);
            if (n == 0) {
                float yv = p + xv * Dv;
                yv *= silu_f(sh_z[s][dl]);
                __nv_bfloat16 h = __float2bfloat16_rn(yv);
                __nv_bfloat16 l = __float2bfloat16_rn(yv - __bfloat162float(h));
                size_t o = (size_t)(off + tb + s) * D_INNER + d;
                y_hi[o] = h;
                y_lo[o] = l;
            }
        }
        __syncthreads();
    }
}

// ---------------- launch ----------------
extern "C" void kernel_launch(void* const* d_in, const int* in_sizes, int n_in,
                              void* d_out, int out_size) {
    const int*   tokens     = (const int*)  d_in[0];
    const float* embed      = (const float*)d_in[1];
    const float* in_norm_w  = (const float*)d_in[2];
    const float* out_norm_w = (const float*)d_in[3];
    const float* norm_w     = (const float*)d_in[4];
    const float* in_proj_w  = (const float*)d_in[5];
    const float* conv_w     = (const float*)d_in[6];
    const float* conv_b     = (const float*)d_in[7];
    const float* x_proj_w   = (const float*)d_in[8];
    const float* dt_proj_w  = (const float*)d_in[9];
    const float* dt_proj_b  = (const float*)d_in[10];
    const float* A_log      = (const float*)d_in[11];
    const float* D_param    = (const float*)d_in[12];
    const float* out_proj_w = (const float*)d_in[13];
    const float* norm_f_w   = (const float*)d_in[14];
    float* out = (float*)d_out;

    float *h, *xz, *xc, *dbl, *dt;
    __nv_bfloat16 *hn_hi, *hn_lo, *xc_hi, *xc_lo, *db_hi, *db_lo, *y_hi, *y_lo;
    __nv_bfloat16 *ip_hi, *ip_lo, *xp_hi, *xp_lo, *dw_hi, *dw_lo, *op_hi, *op_lo;
    cudaGetSymbolAddress((void**)&h,   g_h);
    cudaGetSymbolAddress((void**)&xz,  g_xz);
    cudaGetSymbolAddress((void**)&xc,  g_xc);
    cudaGetSymbolAddress((void**)&dbl, g_dbl);
    cudaGetSymbolAddress((void**)&dt,  g_dt);
    cudaGetSymbolAddress((void**)&hn_hi, g_hn_hi); cudaGetSymbolAddress((void**)&hn_lo, g_hn_lo);
    cudaGetSymbolAddress((void**)&xc_hi, g_xc_hi); cudaGetSymbolAddress((void**)&xc_lo, g_xc_lo);
    cudaGetSymbolAddress((void**)&db_hi, g_db_hi); cudaGetSymbolAddress((void**)&db_lo, g_db_lo);
    cudaGetSymbolAddress((void**)&y_hi,  g_y_hi);  cudaGetSymbolAddress((void**)&y_lo,  g_y_lo);
    cudaGetSymbolAddress((void**)&ip_hi, g_ip_hi); cudaGetSymbolAddress((void**)&ip_lo, g_ip_lo);
    cudaGetSymbolAddress((void**)&xp_hi, g_xp_hi); cudaGetSymbolAddress((void**)&xp_lo, g_xp_lo);
    cudaGetSymbolAddress((void**)&dw_hi, g_dw_hi); cudaGetSymbolAddress((void**)&dw_lo, g_dw_lo);
    cudaGetSymbolAddress((void**)&op_hi, g_op_hi); cudaGetSymbolAddress((void**)&op_lo, g_op_lo);

    cudaFuncSetAttribute(gemm_tc_kernel, cudaFuncAttributeMaxDynamicSharedMemorySize, GSMEM);

    const int MB = (TOTAL + 127) / 128;   // 54

    // launches 1-4: weight splits
    split_kernel<<<(N_LAYERS * IPW_N / 4 + 255) / 256, 256>>>(in_proj_w,  ip_hi, ip_lo, N_LAYERS * IPW_N / 4);
    split_kernel<<<(N_LAYERS * XPW_N / 4 + 255) / 256, 256>>>(x_proj_w,   xp_hi, xp_lo, N_LAYERS * XPW_N / 4);
    split_kernel<<<(N_LAYERS * DTW_N / 4 + 255) / 256, 256>>>(dt_proj_w,  dw_hi, dw_lo, N_LAYERS * DTW_N / 4);
    split_kernel<<<(N_LAYERS * OPW_N / 4 + 255) / 256, 256>>>(out_proj_w, op_hi, op_lo, N_LAYERS * OPW_N / 4);

    // launch 5: embed + rmsnorm(in) + rmsnorm(layer0) + split
    embed_fused_kernel<<<TOTAL, 256>>>(tokens, embed, in_norm_w, norm_w, h, hn_hi, hn_lo);

    for (int l = 0; l < N_LAYERS; l++) {
        if (l > 0)
            rms_split_kernel<<<TOTAL, 256>>>(h, norm_w + l * D_MODEL, hn_hi, hn_lo);

        // launch 6 (l=0): xz = hn @ in_proj_w^T   [TOTAL, 3072]  <- ncu capture target
        gemm_tc_kernel<<<dim3(2 * D_INNER / 128, MB), 256, GSMEM>>>(
            hn_hi, hn_lo, ip_hi + (size_t)l * IPW_N, ip_lo + (size_t)l * IPW_N,
            nullptr, xz, nullptr, nullptr, TOTAL, 2 * D_INNER, D_MODEL, 0);

        conv_kernel<<<(TOTAL * D_INNER / 2 + 255) / 256, 256>>>(
            xz, conv_w + (size_t)l * D_INNER * 4, conv_b + (size_t)l * D_INNER,
            xc, xc_hi, xc_lo);

        // dbl = xc @ x_proj_w^T   [TOTAL, 80]  (epi 3: also split cols [0,48))
        gemm_tc_kernel<<<dim3(1, MB), 256, GSMEM>>>(
            xc_hi, xc_lo, xp_hi + (size_t)l * XPW_N, xp_lo + (size_t)l * XPW_N,
            nullptr, dbl, db_hi, db_lo, TOTAL, 80, D_INNER, 3);

        // dt = softplus(dbl[:, :48] @ dt_proj_w^T + b)   [TOTAL, 1536]
        gemm_tc_kernel<<<dim3(D_INNER / 128, MB), 256, GSMEM>>>(
            db_hi, db_lo, dw_hi + (size_t)l * DTW_N, dw_lo + (size_t)l * DTW_N,
            dt_proj_b + (size_t)l * D_INNER, dt, nullptr, nullptr,
            TOTAL, D_INNER, DT_RANK, 1);

        scan_kernel<<<dim3(D_INNER / 16, NSUBJ), 256>>>(
            xc, dt, dbl, xz,
            A_log + (size_t)l * D_INNER * D_STATE, D_param + (size_t)l * D_INNER,
            y_hi, y_lo);

        // h += y @ out_proj_w^T   [TOTAL, 768]
        gemm_tc_kernel<<<dim3(D_MODEL / 128, MB), 256, GSMEM>>>(
            y_hi, y_lo, op_hi + (size_t)l * OPW_N, op_lo + (size_t)l * OPW_N,
            nullptr, h, nullptr, nullptr, TOTAL, D_MODEL, D_INNER, 2);
    }

    final_kernel<<<TOTAL, 256>>>(h, norm_f_w, out_norm_w, out);
}

// round 16
// speedup vs baseline: 1.3550x; 1.1704x over previous
#include <cuda_runtime.h>
#include <cuda_bf16.h>
#include <cuda_fp16.h>
#include <cstdint>

// ---------------- static problem configuration ----------------
#define TOTAL    6848
#define D_MODEL  768
#define D_INNER  1536
#define D_STATE  16
#define DT_RANK  48
#define NSUBJ    8
#define N_LAYERS 2
#define EPS      1e-5f

__constant__ int c_offsets[NSUBJ + 1] = {0, 1024, 1920, 2688, 3712, 4224, 4864, 5824, 6848};

#define IPW_N (2 * D_INNER * D_MODEL)
#define XPW_N ((DT_RANK + 2 * D_STATE) * D_INNER)
#define DTW_N (D_INNER * DT_RANK)
#define OPW_N (D_MODEL * D_INNER)

// ---------------- scratch (device globals; no runtime allocation) ----------------
__device__ float g_h  [TOTAL * D_MODEL];
__device__ float g_xz [TOTAL * 2 * D_INNER];
__device__ float g_xc [TOTAL * D_INNER];
__device__ float g_dbl[TOTAL * 80];
__device__ float g_dt [TOTAL * D_INNER];

// activations: single fp16
__device__ __half g_hn_h[TOTAL * D_MODEL];
__device__ __half g_xc_h[TOTAL * D_INNER];
__device__ __half g_db_h[TOTAL * DT_RANK];
__device__ __half g_y_h [TOTAL * D_INNER];

// weights: fp16 hi/lo split
__device__ __half g_ip_hi[N_LAYERS * IPW_N], g_ip_lo[N_LAYERS * IPW_N];
__device__ __half g_xp_hi[N_LAYERS * XPW_N], g_xp_lo[N_LAYERS * XPW_N];
__device__ __half g_dw_hi[N_LAYERS * DTW_N], g_dw_lo[N_LAYERS * DTW_N];
__device__ __half g_op_hi[N_LAYERS * OPW_N], g_op_lo[N_LAYERS * OPW_N];

// ---------------- helpers ----------------
__device__ __forceinline__ float blockReduceSum(float v) {
    __shared__ float sh[8];
    __shared__ float total;
    #pragma unroll
    for (int o = 16; o; o >>= 1) v += __shfl_xor_sync(0xffffffffu, v, o);
    if ((threadIdx.x & 31) == 0) sh[threadIdx.x >> 5] = v;
    __syncthreads();
    v = (threadIdx.x < 8) ? sh[threadIdx.x] : 0.f;
    #pragma unroll
    for (int o = 4; o; o >>= 1) v += __shfl_xor_sync(0xffffffffu, v, o);
    if (threadIdx.x == 0) total = v;
    __syncthreads();
    return total;
}

__device__ __forceinline__ float silu_f(float x) { return x / (1.f + __expf(-x)); }

// split fp32 pair into fp16 hi/lo half2
__device__ __forceinline__ void split2h(float f0, float f1, __half2& hi, __half2& lo) {
    hi = __floats2half2_rn(f0, f1);
    lo = __floats2half2_rn(f0 - __half2float(__low2half(hi)),
                           f1 - __half2float(__high2half(hi)));
}

__device__ __forceinline__ void mma_f16(float* c, const uint32_t* a, uint32_t b0, uint32_t b1) {
    asm volatile(
        "mma.sync.aligned.m16n8k16.row.col.f32.f16.f16.f32 "
        "{%0,%1,%2,%3}, {%4,%5,%6,%7}, {%8,%9}, {%0,%1,%2,%3};"
        : "+f"(c[0]), "+f"(c[1]), "+f"(c[2]), "+f"(c[3])
        : "r"(a[0]), "r"(a[1]), "r"(a[2]), "r"(a[3]), "r"(b0), "r"(b1));
}

__device__ __forceinline__ void ldsm4(uint32_t* r, uint32_t addr) {
    asm volatile("ldmatrix.sync.aligned.m8n8.x4.shared.b16 {%0,%1,%2,%3}, [%4];"
        : "=r"(r[0]), "=r"(r[1]), "=r"(r[2]), "=r"(r[3]) : "r"(addr));
}

__device__ __forceinline__ void cp16(uint32_t dst, const void* src, int sz) {
    asm volatile("cp.async.cg.shared.global [%0], [%1], 16, %2;"
                 :: "r"(dst), "l"(src), "r"(sz));
}
#define CP_COMMIT() asm volatile("cp.async.commit_group;")
#define CP_WAIT(n)  asm volatile("cp.async.wait_group %0;" :: "n"(n))

// swizzled smem byte offset inside one 128x32 fp16 tile (64B rows)
__device__ __forceinline__ uint32_t sw_off(int row, int chunk) {
    return (uint32_t)(row * 64 + ((chunk ^ ((row >> 1) & 3)) << 4));
}

// ---------------- weight split kernel (fp32 -> fp16 hi/lo) ----------------
__global__ void __launch_bounds__(256) split_w_kernel(
    const float* __restrict__ src, __half* __restrict__ hi,
    __half* __restrict__ lo, int n4)
{
    int i = blockIdx.x * 256 + threadIdx.x;
    if (i >= n4) return;
    float4 v = ((const float4*)src)[i];
    __half2 h0, l0, h1, l1;
    split2h(v.x, v.y, h0, l0);
    split2h(v.z, v.w, h1, l1);
    ((__half2*)hi)[i * 2]     = h0;
    ((__half2*)hi)[i * 2 + 1] = h1;
    ((__half2*)lo)[i * 2]     = l0;
    ((__half2*)lo)[i * 2 + 1] = l1;
}

// ---------------- embed gather + rmsnorm(in_norm) + rmsnorm(norm_w0) + fp16 ----------
__global__ void __launch_bounds__(256) embed_fused_kernel(
    const int* __restrict__ tokens, const float* __restrict__ embed,
    const float* __restrict__ w_in, const float* __restrict__ w_n0,
    float* __restrict__ hout, __half* __restrict__ hn)
{
    const int row = blockIdx.x;
    const float* xr = embed + (size_t)tokens[row] * D_MODEL;
    float xv[3];
    float s1 = 0.f;
    #pragma unroll
    for (int j = 0; j < 3; j++) {
        int i = threadIdx.x + j * 256;
        float v = xr[i];
        xv[j] = v;
        s1 += v * v;
    }
    float t1 = blockReduceSum(s1);
    float r1 = rsqrtf(t1 / D_MODEL + EPS);
    float hv[3];
    float s2 = 0.f;
    #pragma unroll
    for (int j = 0; j < 3; j++) {
        int i = threadIdx.x + j * 256;
        float v = xv[j] * r1 * w_in[i];
        hv[j] = v;
        hout[row * D_MODEL + i] = v;
        s2 += v * v;
    }
    float t2 = blockReduceSum(s2);
    float r2 = rsqrtf(t2 / D_MODEL + EPS);
    #pragma unroll
    for (int j = 0; j < 3; j++) {
        int i = threadIdx.x + j * 256;
        hn[row * D_MODEL + i] = __float2half_rn(hv[j] * r2 * w_n0[i]);
    }
}

// ---------------- rmsnorm -> fp16 ----------------
__global__ void __launch_bounds__(256) rms_split_kernel(
    const float* __restrict__ x, const float* __restrict__ w,
    __half* __restrict__ hn)
{
    const int row = blockIdx.x;
    const float* xr = x + row * D_MODEL;
    float s = 0.f;
    for (int i = threadIdx.x; i < D_MODEL; i += 256) { float v = xr[i]; s += v * v; }
    float tot = blockReduceSum(s);
    float r = rsqrtf(tot / D_MODEL + EPS);
    for (int p = threadIdx.x; p < D_MODEL / 2; p += 256) {
        float2 v = ((const float2*)xr)[p];
        ((__half2*)hn)[row * (D_MODEL / 2) + p] =
            __floats2half2_rn(v.x * r * w[p * 2], v.y * r * w[p * 2 + 1]);
    }
}

// ---------------- final: rmsnorm(norm_f) then rmsnorm(out_norm) ----------------
__global__ void __launch_bounds__(256) final_kernel(
    const float* __restrict__ x, const float* __restrict__ wf,
    const float* __restrict__ wo, float* __restrict__ out)
{
    const int row = blockIdx.x;
    const float* xr = x + row * D_MODEL;
    float s1 = 0.f, s2 = 0.f;
    for (int i = threadIdx.x; i < D_MODEL; i += 256) {
        float v = xr[i];
        float vw = v * wf[i];
        s1 += v * v;
        s2 += vw * vw;
    }
    float t1 = blockReduceSum(s1);
    float t2 = blockReduceSum(s2);
    float r1 = rsqrtf(t1 / D_MODEL + EPS);
    float m2 = (r1 * r1) * t2 / D_MODEL;
    float r2 = rsqrtf(m2 + EPS);
    for (int i = threadIdx.x; i < D_MODEL; i += 256)
        out[row * D_MODEL + i] = xr[i] * wf[i] * r1 * r2 * wo[i];
}

// ---------------- tensor-core GEMM (2-mma fp16: A plain, W hi/lo split) ----------
// C[M,N] (op)= A[M,K] * W[N,K]^T.  A fp16 single precision operand,
// W pre-split fp16 hi/lo (W = Wh + Wl exactly to ~2^-22).
// Block 128x128, 256 threads (8 warps, warp tile 64x32), BK=32,
// 2-stage cp.async double buffer, ldmatrix, XOR-swizzled smem, 2 CTAs/SM.
// epi: 0 = store, 1 = softplus(acc + bias[n]), 2 = C += acc,
//      3 = store + fp16 cols [0,48) to edb (compact lda 48)
#define GS_STAGE 24576
#define GS_A     0
#define GS_B_HI  8192
#define GS_B_LO  16384
#define GSMEM    (2 * GS_STAGE)

__device__ __forceinline__ void gemm_load_stage(
    uint32_t sb, int tid, int m0, int n0, int k0, int M, int N, int K,
    const __half* __restrict__ A,
    const __half* __restrict__ Wh, const __half* __restrict__ Wl)
{
    #pragma unroll
    for (int half_i = 0; half_i < 2; half_i++) {
        int li = half_i * 256 + tid;        // 0..511
        int row = li >> 2, c = li & 3;
        int k = k0 + c * 8;
        int kin = (k < K) ? 16 : 0;
        int kc  = (k < K) ? k : 0;
        uint32_t off = sw_off(row, c);

        int ar = m0 + row; if (ar >= M) ar = M - 1;
        cp16(sb + GS_A + off, A + (size_t)ar * K + kc, kin);

        int br = n0 + row;
        int bin = (br < N) ? kin : 0;
        int brc = (br < N) ? br : 0;
        size_t bo = (size_t)brc * K + kc;
        cp16(sb + GS_B_HI + off, Wh + bo, bin);
        cp16(sb + GS_B_LO + off, Wl + bo, bin);
    }
}

__global__ void __launch_bounds__(256, 2) gemm_tc_kernel(
    const __half* __restrict__ A,
    const __half* __restrict__ Wh, const __half* __restrict__ Wl,
    const float* __restrict__ bias, float* __restrict__ C,
    __half* __restrict__ edb,
    int M, int N, int K, int epi)
{
    extern __shared__ uint8_t smem[];
    const int tid = threadIdx.x, lane = tid & 31, warp = tid >> 5;
    const int m0 = blockIdx.y * 128, n0 = blockIdx.x * 128;
    const int wm = (warp & 1) * 64, wn = (warp >> 1) * 32;
    const int g = lane >> 2, tg = lane & 3;

    uint32_t sbase = (uint32_t)__cvta_generic_to_shared(smem);

    float acc[4][4][4];
    #pragma unroll
    for (int mi = 0; mi < 4; mi++)
        #pragma unroll
        for (int ni = 0; ni < 4; ni++)
            #pragma unroll
            for (int r = 0; r < 4; r++) acc[mi][ni][r] = 0.f;

    const int KT = (K + 31) >> 5;
    gemm_load_stage(sbase, tid, m0, n0, 0, M, N, K, A, Wh, Wl);
    CP_COMMIT();

    const int mat = lane >> 3, mr = lane & 7;

    for (int kt = 0; kt < KT; kt++) {
        if (kt + 1 < KT) {
            gemm_load_stage(sbase + ((kt + 1) & 1) * GS_STAGE, tid, m0, n0,
                            (kt + 1) * 32, M, N, K, A, Wh, Wl);
            CP_COMMIT();
            CP_WAIT(1);
        } else {
            CP_WAIT(0);
        }
        __syncthreads();

        uint32_t stb  = sbase + (kt & 1) * GS_STAGE;
        uint32_t A_b  = stb + GS_A;
        uint32_t Bh_b = stb + GS_B_HI, Bl_b = stb + GS_B_LO;

        #pragma unroll
        for (int s = 0; s < 2; s++) {
            uint32_t bh[4][2], bl[4][2];
            #pragma unroll
            for (int pair = 0; pair < 2; pair++) {
                int nrow = wn + pair * 16 + ((mat >> 1) << 3) + mr;
                int chunk = s * 2 + (mat & 1);
                uint32_t off = sw_off(nrow, chunk);
                uint32_t r[4];
                ldsm4(r, Bh_b + off);
                bh[pair * 2][0] = r[0]; bh[pair * 2][1] = r[1];
                bh[pair * 2 + 1][0] = r[2]; bh[pair * 2 + 1][1] = r[3];
                ldsm4(r, Bl_b + off);
                bl[pair * 2][0] = r[0]; bl[pair * 2][1] = r[1];
                bl[pair * 2 + 1][0] = r[2]; bl[pair * 2 + 1][1] = r[3];
            }
            #pragma unroll
            for (int mi = 0; mi < 4; mi++) {
                int arow = wm + mi * 16 + ((mat & 1) << 3) + mr;
                int chunk = s * 2 + (mat >> 1);
                uint32_t off = sw_off(arow, chunk);
                uint32_t ah[4];
                ldsm4(ah, A_b + off);
                #pragma unroll
                for (int ni = 0; ni < 4; ni++) {
                    mma_f16(acc[mi][ni], ah, bh[ni][0], bh[ni][1]);
                    mma_f16(acc[mi][ni], ah, bl[ni][0], bl[ni][1]);
                }
            }
        }
        __syncthreads();
    }

    // ---- epilogue ----
    #pragma unroll
    for (int mi = 0; mi < 4; mi++) {
        int mrow0 = m0 + wm + mi * 16 + g;
        int mrow1 = mrow0 + 8;
        #pragma unroll
        for (int ni = 0; ni < 4; ni++) {
            int n = n0 + wn + ni * 8 + 2 * tg;
            if (n >= N) continue;   // N multiple of 8 -> pair-safe
            float* c = acc[mi][ni];
            if (epi == 1) {
                float b0 = bias[n], b1 = bias[n + 1];
                #pragma unroll
                for (int r = 0; r < 4; r++) {
                    float v = c[r] + ((r & 1) ? b1 : b0);
                    c[r] = (v > 20.f) ? v : log1pf(__expf(v));
                }
            }
            if (mrow0 < M) {
                size_t b = (size_t)mrow0 * N + n;
                if (epi == 2) { C[b] += c[0]; C[b + 1] += c[1]; }
                else          { C[b]  = c[0]; C[b + 1]  = c[1]; }
                if (epi == 3 && n < DT_RANK)
                    ((__half2*)edb)[mrow0 * (DT_RANK / 2) + (n >> 1)] =
                        __floats2half2_rn(c[0], c[1]);
            }
            if (mrow1 < M) {
                size_t b = (size_t)mrow1 * N + n;
                if (epi == 2) { C[b] += c[2]; C[b + 1] += c[3]; }
                else          { C[b]  = c[2]; C[b + 1]  = c[3]; }
                if (epi == 3 && n < DT_RANK)
                    ((__half2*)edb)[mrow1 * (DT_RANK / 2) + (n >> 1)] =
                        __floats2half2_rn(c[2], c[3]);
            }
        }
    }
}

// ---------------- causal depthwise conv (k=4) + bias + silu (+ fp16) ----------------
__global__ void __launch_bounds__(256) conv_kernel(
    const float* __restrict__ xz, const float* __restrict__ cw,
    const float* __restrict__ cb, float* __restrict__ xc,
    __half* __restrict__ xc_h)
{
    int p = blockIdx.x * 256 + threadIdx.x;
    if (p >= TOTAL * (D_INNER / 2)) return;
    int t = p / (D_INNER / 2);
    int i = (p - t * (D_INNER / 2)) * 2;
    int t0 = 0;
    #pragma unroll
    for (int s = 1; s < NSUBJ; s++)
        if (t >= c_offsets[s]) t0 = c_offsets[s];

    float o[2];
    #pragma unroll
    for (int u = 0; u < 2; u++) {
        int ch = i + u;
        float w0 = cw[ch * 4 + 0], w1 = cw[ch * 4 + 1], w2 = cw[ch * 4 + 2], w3 = cw[ch * 4 + 3];
        float acc = cb[ch] + w3 * xz[(size_t)t * (2 * D_INNER) + ch];
        if (t - 1 >= t0) acc = fmaf(w2, xz[(size_t)(t - 1) * (2 * D_INNER) + ch], acc);
        if (t - 2 >= t0) acc = fmaf(w1, xz[(size_t)(t - 2) * (2 * D_INNER) + ch], acc);
        if (t - 3 >= t0) acc = fmaf(w0, xz[(size_t)(t - 3) * (2 * D_INNER) + ch], acc);
        o[u] = silu_f(acc);
    }
    ((float2*)xc)[p] = make_float2(o[0], o[1]);
    ((__half2*)xc_h)[p] = __floats2half2_rn(o[0], o[1]);
}

// ---------------- selective scan (+ D skip + silu(z) gate), fp16 output ----------------
__global__ void __launch_bounds__(256) scan_kernel(
    const float* __restrict__ xc, const float* __restrict__ dt,
    const float* __restrict__ dbl, const float* __restrict__ xz,
    const float* __restrict__ A_log, const float* __restrict__ Dp,
    __half* __restrict__ y_h)
{
    const int subj = blockIdx.y;
    const int d0 = blockIdx.x * 16;
    const int off = c_offsets[subj];
    const int L = c_offsets[subj + 1] - off;
    const int tid = threadIdx.x;
    const int dl = tid >> 4;
    const int n  = tid & 15;
    const int d  = d0 + dl;

    const float Acoef = -__expf(A_log[d * D_STATE + n]);
    const float Dv = Dp[d];
    float hc = 0.f;

    __shared__ float sh_dt[64][16], sh_x[64][16], sh_z[64][16], sh_B[64][16], sh_C[64][16];

    for (int tb = 0; tb < L; tb += 64) {
        int nsteps = min(64, L - tb);
        for (int idx = tid; idx < 64 * 16; idx += 256) {
            int tl = idx >> 4, dd = idx & 15;
            if (tl < nsteps) {
                int t = off + tb + tl;
                sh_dt[tl][dd] = dt[(size_t)t * D_INNER + d0 + dd];
                sh_x [tl][dd] = xc[(size_t)t * D_INNER + d0 + dd];
                sh_z [tl][dd] = xz[(size_t)t * (2 * D_INNER) + D_INNER + d0 + dd];
                sh_B [tl][dd] = dbl[(size_t)t * 80 + DT_RANK + dd];
                sh_C [tl][dd] = dbl[(size_t)t * 80 + DT_RANK + D_STATE + dd];
            }
        }
        __syncthreads();
        for (int s = 0; s < nsteps; s++) {
            float dtv = sh_dt[s][dl];
            float xv  = sh_x[s][dl];
            float dA = __expf(dtv * Acoef);
            hc = fmaf(dA, hc, (dtv * xv) * sh_B[s][n]);
            float p = hc * sh_C[s][n];
            p += __shfl_xor_sync(0xffffffffu, p, 1);
            p += __shfl_xor_sync(0xffffffffu, p, 2);
            p += __shfl_xor_sync(0xffffffffu, p, 4);
            p += __shfl_xor_sync(0xffffffffu, p, 8);
            if (n == 0) {
                float yv = p + xv * Dv;
                yv *= silu_f(sh_z[s][dl]);
                y_h[(size_t)(off + tb + s) * D_INNER + d] = __float2half_rn(yv);
            }
        }
        __syncthreads();
    }
}

// ---------------- launch ----------------
extern "C" void kernel_launch(void* const* d_in, const int* in_sizes, int n_in,
                              void* d_out, int out_size) {
    const int*   tokens     = (const int*)  d_in[0];
    const float* embed      = (const float*)d_in[1];
    const float* in_norm_w  = (const float*)d_in[2];
    const float* out_norm_w = (const float*)d_in[3];
    const float* norm_w     = (const float*)d_in[4];
    const float* in_proj_w  = (const float*)d_in[5];
    const float* conv_w     = (const float*)d_in[6];
    const float* conv_b     = (const float*)d_in[7];
    const float* x_proj_w   = (const float*)d_in[8];
    const float* dt_proj_w  = (const float*)d_in[9];
    const float* dt_proj_b  = (const float*)d_in[10];
    const float* A_log      = (const float*)d_in[11];
    const float* D_param    = (const float*)d_in[12];
    const float* out_proj_w = (const float*)d_in[13];
    const float* norm_f_w   = (const float*)d_in[14];
    float* out = (float*)d_out;

    float *h, *xz, *xc, *dbl, *dt;
    __half *hn, *xch, *dbh, *yh;
    __half *ip_hi, *ip_lo, *xp_hi, *xp_lo, *dw_hi, *dw_lo, *op_hi, *op_lo;
    cudaGetSymbolAddress((void**)&h,   g_h);
    cudaGetSymbolAddress((void**)&xz,  g_xz);
    cudaGetSymbolAddress((void**)&xc,  g_xc);
    cudaGetSymbolAddress((void**)&dbl, g_dbl);
    cudaGetSymbolAddress((void**)&dt,  g_dt);
    cudaGetSymbolAddress((void**)&hn,  g_hn_h);
    cudaGetSymbolAddress((void**)&xch, g_xc_h);
    cudaGetSymbolAddress((void**)&dbh, g_db_h);
    cudaGetSymbolAddress((void**)&yh,  g_y_h);
    cudaGetSymbolAddress((void**)&ip_hi, g_ip_hi); cudaGetSymbolAddress((void**)&ip_lo, g_ip_lo);
    cudaGetSymbolAddress((void**)&xp_hi, g_xp_hi); cudaGetSymbolAddress((void**)&xp_lo, g_xp_lo);
    cudaGetSymbolAddress((void**)&dw_hi, g_dw_hi); cudaGetSymbolAddress((void**)&dw_lo, g_dw_lo);
    cudaGetSymbolAddress((void**)&op_hi, g_op_hi); cudaGetSymbolAddress((void**)&op_lo, g_op_lo);

    cudaFuncSetAttribute(gemm_tc_kernel, cudaFuncAttributeMaxDynamicSharedMemorySize, GSMEM);

    const int MB = (TOTAL + 127) / 128;   // 54

    // weight splits (fp16 hi/lo)
    split_w_kernel<<<(N_LAYERS * IPW_N / 4 + 255) / 256, 256>>>(in_proj_w,  ip_hi, ip_lo, N_LAYERS * IPW_N / 4);
    split_w_kernel<<<(N_LAYERS * XPW_N / 4 + 255) / 256, 256>>>(x_proj_w,   xp_hi, xp_lo, N_LAYERS * XPW_N / 4);
    split_w_kernel<<<(N_LAYERS * DTW_N / 4 + 255) / 256, 256>>>(dt_proj_w,  dw_hi, dw_lo, N_LAYERS * DTW_N / 4);
    split_w_kernel<<<(N_LAYERS * OPW_N / 4 + 255) / 256, 256>>>(out_proj_w, op_hi, op_lo, N_LAYERS * OPW_N / 4);

    // embed + rmsnorm(in) + rmsnorm(layer0) -> fp16
    embed_fused_kernel<<<TOTAL, 256>>>(tokens, embed, in_norm_w, norm_w, h, hn);

    for (int l = 0; l < N_LAYERS; l++) {
        if (l > 0)
            rms_split_kernel<<<TOTAL, 256>>>(h, norm_w + l * D_MODEL, hn);

        // xz = hn @ in_proj_w^T   [TOTAL, 3072]
        gemm_tc_kernel<<<dim3(2 * D_INNER / 128, MB), 256, GSMEM>>>(
            hn, ip_hi + (size_t)l * IPW_N, ip_lo + (size_t)l * IPW_N,
            nullptr, xz, nullptr, TOTAL, 2 * D_INNER, D_MODEL, 0);

        conv_kernel<<<(TOTAL * D_INNER / 2 + 255) / 256, 256>>>(
            xz, conv_w + (size_t)l * D_INNER * 4, conv_b + (size_t)l * D_INNER,
            xc, xch);

        // dbl = xc @ x_proj_w^T   [TOTAL, 80]  (epi 3: also fp16 cols [0,48))
        gemm_tc_kernel<<<dim3(1, MB), 256, GSMEM>>>(
            xch, xp_hi + (size_t)l * XPW_N, xp_lo + (size_t)l * XPW_N,
            nullptr, dbl, dbh, TOTAL, 80, D_INNER, 3);

        // dt = softplus(dbl[:, :48] @ dt_proj_w^T + b)   [TOTAL, 1536]
        gemm_tc_kernel<<<dim3(D_INNER / 128, MB), 256, GSMEM>>>(
            dbh, dw_hi + (size_t)l * DTW_N, dw_lo + (size_t)l * DTW_N,
            dt_proj_b + (size_t)l * D_INNER, dt, nullptr,
            TOTAL, D_INNER, DT_RANK, 1);

        scan_kernel<<<dim3(D_INNER / 16, NSUBJ), 256>>>(
            xc, dt, dbl, xz,
            A_log + (size_t)l * D_INNER * D_STATE, D_param + (size_t)l * D_INNER,
            yh);

        // h += y @ out_proj_w^T   [TOTAL, 768]
        gemm_tc_kernel<<<dim3(D_MODEL / 128, MB), 256, GSMEM>>>(
            yh, op_hi + (size_t)l * OPW_N, op_lo + (size_t)l * OPW_N,
            nullptr, h, nullptr, TOTAL, D_MODEL, D_INNER, 2);
    }

    final_kernel<<<TOTAL, 256>>>(h, norm_f_w, out_norm_w, out);
}